// round 9
// baseline (speedup 1.0000x reference)
#include <cuda_runtime.h>
#include <math.h>
#include <stdint.h>

// Problem constants (fixed by the dataset instance)
#define Bsz   16384
#define Csz   2048
#define Ksz   200
#define NCsz  1000
#define SLOTS 32
#define GAPEPS 3e-4f

// GEMM1 (tensor) tiling
#define BM1 128
#define TH1 512
#define SA  33        // float2 row stride for (hi,lo) tiles

// GEMM2 tiling
#define TNO 128
#define RB  128

// ---------------- device scratch (no allocations allowed) ----------------
__device__ float g_proto[Ksz * Csz];                    // normalized prototypes
__device__ __align__(16) float g_fcwT[Ksz * NCsz];      // fc_w transposed: [K][NC]
__device__ int   g_sidx[Bsz * SLOTS];                   // per-row surviving indices
__device__ float g_sval[Bsz * SLOTS];                   // per-row surviving LN'd values
__device__ int   g_fix_cnt;                             // # near-tie rows
__device__ int   g_fix_list[Bsz];                       // their row ids

// ---------------- tf32 helpers ----------------
// cvt.rna.tf32.f32 needs a b32 destination; result bits are a valid f32
// pattern (low mantissa bits zeroed), so reinterpret back to float.
__device__ __forceinline__ float to_tf32(float a) {
    uint32_t r;
    asm("cvt.rna.tf32.f32 %0, %1;" : "=r"(r) : "f"(a));
    return __uint_as_float(r);
}
__device__ __forceinline__ void mma_tf32(float* c,
        uint32_t a0, uint32_t a1, uint32_t a2, uint32_t a3,
        uint32_t b0, uint32_t b1) {
    asm volatile(
        "mma.sync.aligned.m16n8k8.row.col.f32.tf32.tf32.f32 "
        "{%0,%1,%2,%3}, {%4,%5,%6,%7}, {%8,%9}, {%0,%1,%2,%3};"
        : "+f"(c[0]), "+f"(c[1]), "+f"(c[2]), "+f"(c[3])
        : "r"(a0), "r"(a1), "r"(a2), "r"(a3), "r"(b0), "r"(b1));
}

// ---------------- shared LN + top-k select + sparse emit (R3-exact) ----------------
// Returns gap = (19th largest |v|) - (20th largest |v|).
__device__ __forceinline__ float row_select_emit(const float* frow,
        const float* __restrict__ lnw, const float* __restrict__ lnb,
        int ktop, int row, int lane) {
    float f[7];
    float s1 = 0.f;
    #pragma unroll
    for (int j = 0; j < 7; j++) {
        int n = lane + 32 * j;
        float v = (n < Ksz) ? frow[n] : 0.f;
        f[j] = v;
        s1 += v;
    }
    #pragma unroll
    for (int off = 16; off > 0; off >>= 1)
        s1 += __shfl_xor_sync(0xffffffffu, s1, off);
    float mu = s1 / (float)Ksz;
    float s2 = 0.f;
    #pragma unroll
    for (int j = 0; j < 7; j++) {
        int n = lane + 32 * j;
        if (n < Ksz) {
            float d = f[j] - mu;
            s2 = fmaf(d, d, s2);
        }
    }
    #pragma unroll
    for (int off = 16; off > 0; off >>= 1)
        s2 += __shfl_xor_sync(0xffffffffu, s2, off);
    float var  = s2 / (float)Ksz;
    float rstd = 1.f / sqrtf(var + 1e-5f);

    float v[7], av[7], sel[7];
    #pragma unroll
    for (int j = 0; j < 7; j++) {
        int n = lane + 32 * j;
        if (n < Ksz) {
            float z = (f[j] - mu) * rstd * lnw[n] + lnb[n];
            v[j] = z; av[j] = fabsf(z); sel[j] = av[j];
        } else { v[j] = 0.f; av[j] = -1.f; sel[j] = -1.f; }
    }
    float t = 0.f, t19 = 3.4e38f;
    for (int it = 0; it < ktop; it++) {
        float lm = sel[0]; int lj = 0;
        #pragma unroll
        for (int j = 1; j < 7; j++) if (sel[j] > lm) { lm = sel[j]; lj = j; }
        float m = lm;
        #pragma unroll
        for (int off = 16; off > 0; off >>= 1)
            m = fmaxf(m, __shfl_xor_sync(0xffffffffu, m, off));
        unsigned ball = __ballot_sync(0xffffffffu, lm == m);
        int leader = __ffs((int)ball) - 1;
        if (lane == leader) sel[lj] = -2.f;
        if (it == ktop - 2) t19 = m;
        t = m;
    }
    int cnt = 0;
    #pragma unroll
    for (int j = 0; j < 7; j++) {
        bool pred = (av[j] - t > 0.f);
        unsigned msk = __ballot_sync(0xffffffffu, pred);
        if (pred) {
            int pos = cnt + __popc(msk & ((1u << lane) - 1u));
            g_sidx[(size_t)row * SLOTS + pos] = lane + 32 * j;
            g_sval[(size_t)row * SLOTS + pos] = v[j];
        }
        cnt += __popc(msk);
    }
    if (lane == 0) {
        for (int p = cnt; p < ktop; p++) {
            g_sidx[(size_t)row * SLOTS + p] = 0;
            g_sval[(size_t)row * SLOTS + p] = 0.f;
        }
    }
    return t19 - t;
}

// ---------------- reset fixup counter ----------------
__global__ void k_rst_kernel() {
    if (threadIdx.x == 0) g_fix_cnt = 0;
}

// ---------------- normalize prototypes exactly like the reference ----------------
__global__ void k_norm_kernel(const float* __restrict__ concepts) {
    __shared__ float red[256];
    __shared__ float nrm;
    int k = blockIdx.x;
    const float* row = concepts + (size_t)k * Csz;
    float s = 0.f;
    for (int c = threadIdx.x; c < Csz; c += 256) {
        float v = row[c];
        s = fmaf(v, v, s);
    }
    red[threadIdx.x] = s;
    __syncthreads();
    for (int off = 128; off > 0; off >>= 1) {
        if (threadIdx.x < off) red[threadIdx.x] += red[threadIdx.x + off];
        __syncthreads();
    }
    if (threadIdx.x == 0) nrm = fmaxf(sqrtf(red[0]), 1e-12f);
    __syncthreads();
    float n = nrm;
    for (int c = threadIdx.x; c < Csz; c += 256)
        g_proto[(size_t)k * Csz + c] = row[c] / n;
}

// ---------------- tiled transpose fc_w [NC,K] -> [K,NC] ----------------
__global__ void k_tr_kernel(const float* __restrict__ fc_w) {
    __shared__ float tile[32][33];
    const int n0 = blockIdx.x * 32;
    const int k0 = blockIdx.y * 32;
    const int tx = threadIdx.x;
    const int ty = threadIdx.y;
    #pragma unroll
    for (int i = 0; i < 32; i += 8) {
        int n = n0 + ty + i, k = k0 + tx;
        tile[ty + i][tx] = (n < NCsz && k < Ksz) ? fc_w[(size_t)n * Ksz + k] : 0.f;
    }
    __syncthreads();
    #pragma unroll
    for (int i = 0; i < 32; i += 8) {
        int k = k0 + ty + i, n = n0 + tx;
        if (k < Ksz && n < NCsz)
            g_fcwT[(size_t)k * NCsz + n] = tile[tx][ty + i];
    }
}

// ---------------- GEMM1: tf32 3-pass tensor-core + fused LN/top-k ----------------
// CTA: 512 thr, tile M=128 x N=224(200). Warp (wm=wid&3, wn=wid>>2): m32 x n56.
__global__ __launch_bounds__(TH1, 1)
void k_main_kernel(const float* __restrict__ x,
                   const float* __restrict__ lnw,
                   const float* __restrict__ lnb,
                   const int*   __restrict__ dfi) {
    extern __shared__ float dyn[];
    float2* sxA  = (float2*)dyn;                 // [128][SA] (hi,lo)
    float2* spB  = sxA + BM1 * SA;               // [224][SA] (hi,lo)
    float*  feat = (float*)(spB + 224 * SA);     // [128][200]

    const int tid  = threadIdx.x;
    const int lane = tid & 31;
    const int wid  = tid >> 5;                   // 0..15
    const int wm   = wid & 3;                    // m block (32 rows)
    const int wn   = wid >> 2;                   // n block (56 cols)
    const int bm0  = blockIdx.x * BM1;

    // zero padded proto rows 200..223 once (never rewritten)
    for (int q = tid; q < 24 * SA; q += TH1)
        spB[200 * SA + q] = make_float2(0.f, 0.f);

    float acc[2][7][4];
    #pragma unroll
    for (int f = 0; f < 2; f++)
        #pragma unroll
        for (int nf = 0; nf < 7; nf++)
            #pragma unroll
            for (int q = 0; q < 4; q++) acc[f][nf][q] = 0.f;

    const int xr = tid >> 2;                     // x-loader row 0..127
    const int xk = (tid & 3) * 8;                // x-loader k offset

    for (int k0 = 0; k0 < Csz; k0 += 32) {
        __syncthreads();
        // x tile: 128x32, split hi/lo
        {
            const float4* p = reinterpret_cast<const float4*>(
                x + (size_t)(bm0 + xr) * Csz + k0 + xk);
            float4 v0 = p[0], v1 = p[1];
            float vv[8] = {v0.x, v0.y, v0.z, v0.w, v1.x, v1.y, v1.z, v1.w};
            #pragma unroll
            for (int i = 0; i < 8; i++) {
                float h = to_tf32(vv[i]);
                float l = to_tf32(vv[i] - h);
                sxA[xr * SA + xk + i] = make_float2(h, l);
            }
        }
        // proto tile: 200x32, split hi/lo
        for (int q = tid; q < 200 * 8; q += TH1) {
            int n = q >> 3, kq = (q & 7) * 4;
            float4 v = *reinterpret_cast<const float4*>(
                g_proto + (size_t)n * Csz + k0 + kq);
            float vv[4] = {v.x, v.y, v.z, v.w};
            #pragma unroll
            for (int i = 0; i < 4; i++) {
                float h = to_tf32(vv[i]);
                float l = to_tf32(vv[i] - h);
                spB[n * SA + kq + i] = make_float2(h, l);
            }
        }
        __syncthreads();

        #pragma unroll
        for (int ks = 0; ks < 4; ks++) {
            const int kc = ks * 8 + (lane & 3);
            const int ra = wm * 32 + (lane >> 2);
            float2 Af[2][4];
            #pragma unroll
            for (int f = 0; f < 2; f++) {
                int rb = ra + f * 16;
                Af[f][0] = sxA[rb * SA + kc];
                Af[f][1] = sxA[(rb + 8) * SA + kc];
                Af[f][2] = sxA[rb * SA + kc + 4];
                Af[f][3] = sxA[(rb + 8) * SA + kc + 4];
            }
            #pragma unroll
            for (int nf = 0; nf < 7; nf++) {
                int nn = wn * 56 + nf * 8 + (lane >> 2);
                float2 B0 = spB[nn * SA + kc];
                float2 B1 = spB[nn * SA + kc + 4];
                uint32_t b0h = __float_as_uint(B0.x), b1h = __float_as_uint(B1.x);
                uint32_t b0l = __float_as_uint(B0.y), b1l = __float_as_uint(B1.y);
                #pragma unroll
                for (int f = 0; f < 2; f++) {
                    uint32_t a0h = __float_as_uint(Af[f][0].x);
                    uint32_t a1h = __float_as_uint(Af[f][1].x);
                    uint32_t a2h = __float_as_uint(Af[f][2].x);
                    uint32_t a3h = __float_as_uint(Af[f][3].x);
                    uint32_t a0l = __float_as_uint(Af[f][0].y);
                    uint32_t a1l = __float_as_uint(Af[f][1].y);
                    uint32_t a2l = __float_as_uint(Af[f][2].y);
                    uint32_t a3l = __float_as_uint(Af[f][3].y);
                    mma_tf32(acc[f][nf], a0h, a1h, a2h, a3h, b0h, b1h); // Ah*Bh
                    mma_tf32(acc[f][nf], a0h, a1h, a2h, a3h, b0l, b1l); // Ah*Bl
                    mma_tf32(acc[f][nf], a0l, a1l, a2l, a3l, b0h, b1h); // Al*Bh
                }
            }
        }
    }
    __syncthreads();

    // scatter accumulators to feat[128][200]
    #pragma unroll
    for (int f = 0; f < 2; f++)
        #pragma unroll
        for (int nf = 0; nf < 7; nf++) {
            int row = wm * 32 + f * 16 + (lane >> 2);
            int col = wn * 56 + nf * 8 + 2 * (lane & 3);
            if (col < Ksz) {
                feat[row * Ksz + col]           = acc[f][nf][0];
                feat[row * Ksz + col + 1]       = acc[f][nf][1];
                feat[(row + 8) * Ksz + col]     = acc[f][nf][2];
                feat[(row + 8) * Ksz + col + 1] = acc[f][nf][3];
            }
        }
    __syncthreads();

    // epilogue: each warp handles 8 rows
    const int ktop = Ksz - *dfi;
    for (int rr = 0; rr < 8; rr++) {
        int rloc = wid * 8 + rr;
        int row  = bm0 + rloc;
        float gap = row_select_emit(&feat[rloc * Ksz], lnw, lnb, ktop, row, lane);
        if (lane == 0 && gap < GAPEPS) {
            int p = atomicAdd(&g_fix_cnt, 1);
            g_fix_list[p] = row;
        }
    }
}

// ---------------- fixup: recompute near-tie rows with R3-exact fp32 ----------------
__global__ __launch_bounds__(256, 1)
void k_fix_kernel(const float* __restrict__ x,
                  const float* __restrict__ lnw,
                  const float* __restrict__ lnb,
                  const int*   __restrict__ dfi) {
    __shared__ float xrow[Csz];
    __shared__ float sfeat[224];
    const int tid  = threadIdx.x;
    const int lane = tid & 31;
    const int nfix = g_fix_cnt;
    const int ktop = Ksz - *dfi;

    for (int i = blockIdx.x; i < nfix; i += gridDim.x) {
        int row = g_fix_list[i];
        __syncthreads();
        for (int q = tid; q < Csz / 4; q += 256)
            *reinterpret_cast<float4*>(&xrow[q * 4]) =
                *reinterpret_cast<const float4*>(&x[(size_t)row * Csz + q * 4]);
        __syncthreads();
        if (tid < Ksz) {
            const float* p = g_proto + (size_t)tid * Csz;
            float a = 0.f;
            for (int c = 0; c < Csz; c += 32) {
                float aT = 0.f;
                #pragma unroll 8
                for (int kk = 0; kk < 32; kk++)
                    aT = fmaf(xrow[c + kk], p[c + kk], aT);   // R3 chunk chain
                a += aT;                                       // R3 chunk merge
            }
            sfeat[tid] = a;
        }
        __syncthreads();
        if (tid < 32)
            row_select_emit(sfeat, lnw, lnb, ktop, row, lane);
    }
}

// ---------------- sparse GEMM2 v4 (round-6 winner, unchanged) ----------------
__global__ __launch_bounds__(256, 2)
void k_out_kernel(const float* __restrict__ fcb,
                  const int*   __restrict__ dfi,
                  float* __restrict__ out) {
    extern __shared__ float4 ws4[];                 // [Ksz][32] float4 = 100KB
    float2* pk = (float2*)(ws4 + Ksz * 32);         // [32][SLOTS] packed (val, idx)

    const int tid  = threadIdx.x;
    const int lane = tid & 31;
    const int wid  = tid >> 5;
    const int cb   = blockIdx.y;
    const int col0 = cb * TNO + lane * 4;
    const bool vall = (col0 + 3) < NCsz;

    for (int q = tid; q < Ksz * 32; q += 256) {
        int k = q >> 5, t4 = q & 31;
        int c = cb * TNO + t4 * 4;
        float4 w;
        if (c + 3 < NCsz) {
            w = *reinterpret_cast<const float4*>(&g_fcwT[(size_t)k * NCsz + c]);
        } else {
            w.x = (c + 0 < NCsz) ? g_fcwT[(size_t)k * NCsz + c + 0] : 0.f;
            w.y = (c + 1 < NCsz) ? g_fcwT[(size_t)k * NCsz + c + 1] : 0.f;
            w.z = (c + 2 < NCsz) ? g_fcwT[(size_t)k * NCsz + c + 2] : 0.f;
            w.w = 0.f;
        }
        ws4[q] = w;
    }

    float4 bb;
    bb.x = (col0 + 0 < NCsz) ? fcb[col0 + 0] : 0.f;
    bb.y = (col0 + 1 < NCsz) ? fcb[col0 + 1] : 0.f;
    bb.z = (col0 + 2 < NCsz) ? fcb[col0 + 2] : 0.f;
    bb.w = (col0 + 3 < NCsz) ? fcb[col0 + 3] : 0.f;
    const int ktop = Ksz - *dfi;
    const int r0   = blockIdx.x * RB;

    for (int batch = 0; batch < RB; batch += 32) {
        __syncthreads();
        for (int q = tid; q < 32 * ktop; q += 256) {
            int r = q / ktop, j = q - r * ktop;
            size_t g = (size_t)(r0 + batch + r) * SLOTS + j;
            pk[r * SLOTS + j] = make_float2(g_sval[g], __int_as_float(g_sidx[g]));
        }
        __syncthreads();

        float4 acc[4];
        #pragma unroll
        for (int r = 0; r < 4; r++) acc[r] = make_float4(0.f, 0.f, 0.f, 0.f);
        const float2* pkr = pk + (wid * 4) * SLOTS;
        #pragma unroll 5
        for (int j = 0; j < ktop; j++) {
            #pragma unroll
            for (int r = 0; r < 4; r++) {
                float2 p = pkr[r * SLOTS + j];
                int idx  = __float_as_int(p.y);
                float4 w = ws4[idx * 32 + lane];
                acc[r].x = fmaf(p.x, w.x, acc[r].x);
                acc[r].y = fmaf(p.x, w.y, acc[r].y);
                acc[r].z = fmaf(p.x, w.z, acc[r].z);
                acc[r].w = fmaf(p.x, w.w, acc[r].w);
            }
        }
        #pragma unroll
        for (int r = 0; r < 4; r++) {
            size_t row = (size_t)(r0 + batch + wid * 4 + r);
            if (vall) {
                float4 o = make_float4(acc[r].x + bb.x, acc[r].y + bb.y,
                                       acc[r].z + bb.z, acc[r].w + bb.w);
                *reinterpret_cast<float4*>(&out[row * NCsz + col0]) = o;
            } else {
                if (col0 + 0 < NCsz) out[row * NCsz + col0 + 0] = acc[r].x + bb.x;
                if (col0 + 1 < NCsz) out[row * NCsz + col0 + 1] = acc[r].y + bb.y;
                if (col0 + 2 < NCsz) out[row * NCsz + col0 + 2] = acc[r].z + bb.z;
            }
        }
    }
}

// ---------------- launch ----------------
extern "C" void kernel_launch(void* const* d_in, const int* in_sizes, int n_in,
                              void* d_out, int out_size) {
    const float* x        = (const float*)d_in[0];
    const float* concepts = (const float*)d_in[1];
    const float* lnw      = (const float*)d_in[2];
    const float* lnb      = (const float*)d_in[3];
    const float* fcw      = (const float*)d_in[4];
    const float* fcb      = (const float*)d_in[5];
    const int*   dfi      = (const int*)d_in[6];
    float* out = (float*)d_out;

    const int smem1 = (BM1 * SA + 224 * SA) * (int)sizeof(float2)
                    + BM1 * Ksz * (int)sizeof(float);            // 195,328 B
    const int smem2 = Ksz * 32 * (int)sizeof(float4)
                    + 32 * SLOTS * (int)sizeof(float2);          // 108,544 B
    cudaFuncSetAttribute(k_main_kernel,
                         cudaFuncAttributeMaxDynamicSharedMemorySize, smem1);
    cudaFuncSetAttribute(k_out_kernel,
                         cudaFuncAttributeMaxDynamicSharedMemorySize, smem2);

    k_rst_kernel<<<1, 32>>>();
    k_norm_kernel<<<Ksz, 256>>>(concepts);
    dim3 trg((NCsz + 31) / 32, (Ksz + 31) / 32);
    k_tr_kernel<<<trg, dim3(32, 8)>>>(fcw);
    k_main_kernel<<<Bsz / BM1, TH1, smem1>>>(x, lnw, lnb, dfi);
    k_fix_kernel<<<120, 256>>>(x, lnw, lnb, dfi);
    dim3 g2(Bsz / RB, (NCsz + TNO - 1) / TNO);
    k_out_kernel<<<g2, 256, smem2>>>(fcb, dfi, out);
}

// round 10
// speedup vs baseline: 1.1191x; 1.1191x over previous
#include <cuda_runtime.h>
#include <math.h>
#include <stdint.h>

// Problem constants (fixed by the dataset instance)
#define Bsz   16384
#define Csz   2048
#define Ksz   200
#define NCsz  1000
#define SLOTS 32
#define GAPEPS 3e-4f

// GEMM1 (tensor) tiling
#define BM1 64
#define TH1 256
#define SA  36        // float2 row stride: 36 mod 16 = 4 -> max 2-way bank conflicts

// GEMM2 tiling
#define TNO 128
#define RB  128

// ---------------- device scratch (no allocations allowed) ----------------
__device__ float g_proto[Ksz * Csz];                    // normalized prototypes
__device__ __align__(16) float g_fcwT[Ksz * NCsz];      // fc_w transposed: [K][NC]
__device__ int   g_sidx[Bsz * SLOTS];                   // per-row surviving indices
__device__ float g_sval[Bsz * SLOTS];                   // per-row surviving LN'd values
__device__ int   g_fix_cnt;                             // # near-tie rows
__device__ int   g_fix_list[Bsz];                       // their row ids

// ---------------- tf32 helpers ----------------
__device__ __forceinline__ float to_tf32(float a) {
    uint32_t r;
    asm("cvt.rna.tf32.f32 %0, %1;" : "=r"(r) : "f"(a));
    return __uint_as_float(r);
}
__device__ __forceinline__ void mma_tf32(float* c,
        uint32_t a0, uint32_t a1, uint32_t a2, uint32_t a3,
        uint32_t b0, uint32_t b1) {
    asm volatile(
        "mma.sync.aligned.m16n8k8.row.col.f32.tf32.tf32.f32 "
        "{%0,%1,%2,%3}, {%4,%5,%6,%7}, {%8,%9}, {%0,%1,%2,%3};"
        : "+f"(c[0]), "+f"(c[1]), "+f"(c[2]), "+f"(c[3])
        : "r"(a0), "r"(a1), "r"(a2), "r"(a3), "r"(b0), "r"(b1));
}

// ---------------- shared LN + top-k select + sparse emit (R3-exact) ----------------
// Returns gap = (19th largest |v|) - (20th largest |v|).
__device__ __forceinline__ float row_select_emit(const float* frow,
        const float* __restrict__ lnw, const float* __restrict__ lnb,
        int ktop, int row, int lane) {
    float f[7];
    float s1 = 0.f;
    #pragma unroll
    for (int j = 0; j < 7; j++) {
        int n = lane + 32 * j;
        float v = (n < Ksz) ? frow[n] : 0.f;
        f[j] = v;
        s1 += v;
    }
    #pragma unroll
    for (int off = 16; off > 0; off >>= 1)
        s1 += __shfl_xor_sync(0xffffffffu, s1, off);
    float mu = s1 / (float)Ksz;
    float s2 = 0.f;
    #pragma unroll
    for (int j = 0; j < 7; j++) {
        int n = lane + 32 * j;
        if (n < Ksz) {
            float d = f[j] - mu;
            s2 = fmaf(d, d, s2);
        }
    }
    #pragma unroll
    for (int off = 16; off > 0; off >>= 1)
        s2 += __shfl_xor_sync(0xffffffffu, s2, off);
    float var  = s2 / (float)Ksz;
    float rstd = 1.f / sqrtf(var + 1e-5f);

    float v[7], av[7], sel[7];
    #pragma unroll
    for (int j = 0; j < 7; j++) {
        int n = lane + 32 * j;
        if (n < Ksz) {
            float z = (f[j] - mu) * rstd * lnw[n] + lnb[n];
            v[j] = z; av[j] = fabsf(z); sel[j] = av[j];
        } else { v[j] = 0.f; av[j] = -1.f; sel[j] = -1.f; }
    }
    float t = 0.f, t19 = 3.4e38f;
    for (int it = 0; it < ktop; it++) {
        float lm = sel[0]; int lj = 0;
        #pragma unroll
        for (int j = 1; j < 7; j++) if (sel[j] > lm) { lm = sel[j]; lj = j; }
        float m = lm;
        #pragma unroll
        for (int off = 16; off > 0; off >>= 1)
            m = fmaxf(m, __shfl_xor_sync(0xffffffffu, m, off));
        unsigned ball = __ballot_sync(0xffffffffu, lm == m);
        int leader = __ffs((int)ball) - 1;
        if (lane == leader) sel[lj] = -2.f;
        if (it == ktop - 2) t19 = m;
        t = m;
    }
    int cnt = 0;
    #pragma unroll
    for (int j = 0; j < 7; j++) {
        bool pred = (av[j] - t > 0.f);
        unsigned msk = __ballot_sync(0xffffffffu, pred);
        if (pred) {
            int pos = cnt + __popc(msk & ((1u << lane) - 1u));
            g_sidx[(size_t)row * SLOTS + pos] = lane + 32 * j;
            g_sval[(size_t)row * SLOTS + pos] = v[j];
        }
        cnt += __popc(msk);
    }
    if (lane == 0) {
        for (int p = cnt; p < ktop; p++) {
            g_sidx[(size_t)row * SLOTS + p] = 0;
            g_sval[(size_t)row * SLOTS + p] = 0.f;
        }
    }
    return t19 - t;
}

// ---------------- reset fixup counter ----------------
__global__ void k_rst_kernel() {
    if (threadIdx.x == 0) g_fix_cnt = 0;
}

// ---------------- normalize prototypes exactly like the reference ----------------
__global__ void k_norm_kernel(const float* __restrict__ concepts) {
    __shared__ float red[256];
    __shared__ float nrm;
    int k = blockIdx.x;
    const float* row = concepts + (size_t)k * Csz;
    float s = 0.f;
    for (int c = threadIdx.x; c < Csz; c += 256) {
        float v = row[c];
        s = fmaf(v, v, s);
    }
    red[threadIdx.x] = s;
    __syncthreads();
    for (int off = 128; off > 0; off >>= 1) {
        if (threadIdx.x < off) red[threadIdx.x] += red[threadIdx.x + off];
        __syncthreads();
    }
    if (threadIdx.x == 0) nrm = fmaxf(sqrtf(red[0]), 1e-12f);
    __syncthreads();
    float n = nrm;
    for (int c = threadIdx.x; c < Csz; c += 256)
        g_proto[(size_t)k * Csz + c] = row[c] / n;
}

// ---------------- tiled transpose fc_w [NC,K] -> [K,NC] ----------------
__global__ void k_tr_kernel(const float* __restrict__ fc_w) {
    __shared__ float tile[32][33];
    const int n0 = blockIdx.x * 32;
    const int k0 = blockIdx.y * 32;
    const int tx = threadIdx.x;
    const int ty = threadIdx.y;
    #pragma unroll
    for (int i = 0; i < 32; i += 8) {
        int n = n0 + ty + i, k = k0 + tx;
        tile[ty + i][tx] = (n < NCsz && k < Ksz) ? fc_w[(size_t)n * Ksz + k] : 0.f;
    }
    __syncthreads();
    #pragma unroll
    for (int i = 0; i < 32; i += 8) {
        int k = k0 + ty + i, n = n0 + tx;
        if (k < Ksz && n < NCsz)
            g_fcwT[(size_t)k * NCsz + n] = tile[tx][ty + i];
    }
}

// ---------------- GEMM1: tf32 3-pass tensor-core + fused LN/top-k ----------------
// CTA: 256 thr, tile M=64 x N=224(200). Warp (wm=wid&1, wn=wid>>1): m32 x n56.
// Per-(row,col) mma sequence identical to round 9 -> bit-identical feat.
__global__ __launch_bounds__(TH1, 2)
void k_main_kernel(const float* __restrict__ x,
                   const float* __restrict__ lnw,
                   const float* __restrict__ lnb,
                   const int*   __restrict__ dfi) {
    extern __shared__ float dyn[];
    float2* sxA  = (float2*)dyn;                 // [64][SA] (hi,lo)
    float2* spB  = sxA + BM1 * SA;               // [224][SA] (hi,lo)
    float*  feat = dyn;                          // [64][200] — aliases tiles (post-mainloop only)

    const int tid  = threadIdx.x;
    const int lane = tid & 31;
    const int wid  = tid >> 5;                   // 0..7
    const int wm   = wid & 1;                    // m block (32 rows)
    const int wn   = wid >> 1;                   // n block (56 cols)
    const int bm0  = blockIdx.x * BM1;

    // zero padded proto rows 200..223 once (never rewritten)
    for (int q = tid; q < 24 * SA; q += TH1)
        spB[200 * SA + q] = make_float2(0.f, 0.f);

    float acc[2][7][4];
    #pragma unroll
    for (int f = 0; f < 2; f++)
        #pragma unroll
        for (int nf = 0; nf < 7; nf++)
            #pragma unroll
            for (int q = 0; q < 4; q++) acc[f][nf][q] = 0.f;

    const int xr = tid >> 2;                     // x-loader row 0..63
    const int xk = (tid & 3) * 8;                // x-loader k offset

    for (int k0 = 0; k0 < Csz; k0 += 32) {
        __syncthreads();
        // x tile: 64x32, split hi/lo
        {
            const float4* p = reinterpret_cast<const float4*>(
                x + (size_t)(bm0 + xr) * Csz + k0 + xk);
            float4 v0 = p[0], v1 = p[1];
            float vv[8] = {v0.x, v0.y, v0.z, v0.w, v1.x, v1.y, v1.z, v1.w};
            #pragma unroll
            for (int i = 0; i < 8; i++) {
                float h = to_tf32(vv[i]);
                float l = to_tf32(vv[i] - h);
                sxA[xr * SA + xk + i] = make_float2(h, l);
            }
        }
        // proto tile: 200x32, split hi/lo
        for (int q = tid; q < 200 * 8; q += TH1) {
            int n = q >> 3, kq = (q & 7) * 4;
            float4 v = *reinterpret_cast<const float4*>(
                g_proto + (size_t)n * Csz + k0 + kq);
            float vv[4] = {v.x, v.y, v.z, v.w};
            #pragma unroll
            for (int i = 0; i < 4; i++) {
                float h = to_tf32(vv[i]);
                float l = to_tf32(vv[i] - h);
                spB[n * SA + kq + i] = make_float2(h, l);
            }
        }
        __syncthreads();

        #pragma unroll
        for (int ks = 0; ks < 4; ks++) {
            const int kc = ks * 8 + (lane & 3);
            const int ra = wm * 32 + (lane >> 2);
            float2 Af[2][4];
            #pragma unroll
            for (int f = 0; f < 2; f++) {
                int rb = ra + f * 16;
                Af[f][0] = sxA[rb * SA + kc];
                Af[f][1] = sxA[(rb + 8) * SA + kc];
                Af[f][2] = sxA[rb * SA + kc + 4];
                Af[f][3] = sxA[(rb + 8) * SA + kc + 4];
            }
            #pragma unroll
            for (int nf = 0; nf < 7; nf++) {
                int nn = wn * 56 + nf * 8 + (lane >> 2);
                float2 B0 = spB[nn * SA + kc];
                float2 B1 = spB[nn * SA + kc + 4];
                uint32_t b0h = __float_as_uint(B0.x), b1h = __float_as_uint(B1.x);
                uint32_t b0l = __float_as_uint(B0.y), b1l = __float_as_uint(B1.y);
                #pragma unroll
                for (int f = 0; f < 2; f++) {
                    uint32_t a0h = __float_as_uint(Af[f][0].x);
                    uint32_t a1h = __float_as_uint(Af[f][1].x);
                    uint32_t a2h = __float_as_uint(Af[f][2].x);
                    uint32_t a3h = __float_as_uint(Af[f][3].x);
                    uint32_t a0l = __float_as_uint(Af[f][0].y);
                    uint32_t a1l = __float_as_uint(Af[f][1].y);
                    uint32_t a2l = __float_as_uint(Af[f][2].y);
                    uint32_t a3l = __float_as_uint(Af[f][3].y);
                    mma_tf32(acc[f][nf], a0h, a1h, a2h, a3h, b0h, b1h); // Ah*Bh
                    mma_tf32(acc[f][nf], a0h, a1h, a2h, a3h, b0l, b1l); // Ah*Bl
                    mma_tf32(acc[f][nf], a0l, a1l, a2l, a3l, b0h, b1h); // Al*Bh
                }
            }
        }
    }
    __syncthreads();   // all tile reads done; feat may now alias the tile buffers

    // scatter accumulators to feat[64][200]
    #pragma unroll
    for (int f = 0; f < 2; f++)
        #pragma unroll
        for (int nf = 0; nf < 7; nf++) {
            int row = wm * 32 + f * 16 + (lane >> 2);
            int col = wn * 56 + nf * 8 + 2 * (lane & 3);
            if (col < Ksz) {
                feat[row * Ksz + col]           = acc[f][nf][0];
                feat[row * Ksz + col + 1]       = acc[f][nf][1];
                feat[(row + 8) * Ksz + col]     = acc[f][nf][2];
                feat[(row + 8) * Ksz + col + 1] = acc[f][nf][3];
            }
        }
    __syncthreads();

    // epilogue: each warp handles 8 rows
    const int ktop = Ksz - *dfi;
    for (int rr = 0; rr < 8; rr++) {
        int rloc = wid * 8 + rr;
        int row  = bm0 + rloc;
        float gap = row_select_emit(&feat[rloc * Ksz], lnw, lnb, ktop, row, lane);
        if (lane == 0 && gap < GAPEPS) {
            int p = atomicAdd(&g_fix_cnt, 1);
            g_fix_list[p] = row;
        }
    }
}

// ---------------- fixup: recompute near-tie rows with R3-exact fp32 ----------------
__global__ __launch_bounds__(256, 1)
void k_fix_kernel(const float* __restrict__ x,
                  const float* __restrict__ lnw,
                  const float* __restrict__ lnb,
                  const int*   __restrict__ dfi) {
    __shared__ float xrow[Csz];
    __shared__ float sfeat[224];
    const int tid  = threadIdx.x;
    const int lane = tid & 31;
    const int nfix = g_fix_cnt;
    const int ktop = Ksz - *dfi;

    for (int i = blockIdx.x; i < nfix; i += gridDim.x) {
        int row = g_fix_list[i];
        __syncthreads();
        for (int q = tid; q < Csz / 4; q += 256)
            *reinterpret_cast<float4*>(&xrow[q * 4]) =
                *reinterpret_cast<const float4*>(&x[(size_t)row * Csz + q * 4]);
        __syncthreads();
        if (tid < Ksz) {
            const float* p = g_proto + (size_t)tid * Csz;
            float a = 0.f;
            for (int c = 0; c < Csz; c += 32) {
                float aT = 0.f;
                #pragma unroll 8
                for (int kk = 0; kk < 32; kk++)
                    aT = fmaf(xrow[c + kk], p[c + kk], aT);   // R3 chunk chain
                a += aT;                                       // R3 chunk merge
            }
            sfeat[tid] = a;
        }
        __syncthreads();
        if (tid < 32)
            row_select_emit(sfeat, lnw, lnb, ktop, row, lane);
    }
}

// ---------------- sparse GEMM2 v4 (round-6 winner, unchanged) ----------------
__global__ __launch_bounds__(256, 2)
void k_out_kernel(const float* __restrict__ fcb,
                  const int*   __restrict__ dfi,
                  float* __restrict__ out) {
    extern __shared__ float4 ws4[];                 // [Ksz][32] float4 = 100KB
    float2* pk = (float2*)(ws4 + Ksz * 32);         // [32][SLOTS] packed (val, idx)

    const int tid  = threadIdx.x;
    const int lane = tid & 31;
    const int wid  = tid >> 5;
    const int cb   = blockIdx.y;
    const int col0 = cb * TNO + lane * 4;
    const bool vall = (col0 + 3) < NCsz;

    for (int q = tid; q < Ksz * 32; q += 256) {
        int k = q >> 5, t4 = q & 31;
        int c = cb * TNO + t4 * 4;
        float4 w;
        if (c + 3 < NCsz) {
            w = *reinterpret_cast<const float4*>(&g_fcwT[(size_t)k * NCsz + c]);
        } else {
            w.x = (c + 0 < NCsz) ? g_fcwT[(size_t)k * NCsz + c + 0] : 0.f;
            w.y = (c + 1 < NCsz) ? g_fcwT[(size_t)k * NCsz + c + 1] : 0.f;
            w.z = (c + 2 < NCsz) ? g_fcwT[(size_t)k * NCsz + c + 2] : 0.f;
            w.w = 0.f;
        }
        ws4[q] = w;
    }

    float4 bb;
    bb.x = (col0 + 0 < NCsz) ? fcb[col0 + 0] : 0.f;
    bb.y = (col0 + 1 < NCsz) ? fcb[col0 + 1] : 0.f;
    bb.z = (col0 + 2 < NCsz) ? fcb[col0 + 2] : 0.f;
    bb.w = (col0 + 3 < NCsz) ? fcb[col0 + 3] : 0.f;
    const int ktop = Ksz - *dfi;
    const int r0   = blockIdx.x * RB;

    for (int batch = 0; batch < RB; batch += 32) {
        __syncthreads();
        for (int q = tid; q < 32 * ktop; q += 256) {
            int r = q / ktop, j = q - r * ktop;
            size_t g = (size_t)(r0 + batch + r) * SLOTS + j;
            pk[r * SLOTS + j] = make_float2(g_sval[g], __int_as_float(g_sidx[g]));
        }
        __syncthreads();

        float4 acc[4];
        #pragma unroll
        for (int r = 0; r < 4; r++) acc[r] = make_float4(0.f, 0.f, 0.f, 0.f);
        const float2* pkr = pk + (wid * 4) * SLOTS;
        #pragma unroll 5
        for (int j = 0; j < ktop; j++) {
            #pragma unroll
            for (int r = 0; r < 4; r++) {
                float2 p = pkr[r * SLOTS + j];
                int idx  = __float_as_int(p.y);
                float4 w = ws4[idx * 32 + lane];
                acc[r].x = fmaf(p.x, w.x, acc[r].x);
                acc[r].y = fmaf(p.x, w.y, acc[r].y);
                acc[r].z = fmaf(p.x, w.z, acc[r].z);
                acc[r].w = fmaf(p.x, w.w, acc[r].w);
            }
        }
        #pragma unroll
        for (int r = 0; r < 4; r++) {
            size_t row = (size_t)(r0 + batch + wid * 4 + r);
            if (vall) {
                float4 o = make_float4(acc[r].x + bb.x, acc[r].y + bb.y,
                                       acc[r].z + bb.z, acc[r].w + bb.w);
                *reinterpret_cast<float4*>(&out[row * NCsz + col0]) = o;
            } else {
                if (col0 + 0 < NCsz) out[row * NCsz + col0 + 0] = acc[r].x + bb.x;
                if (col0 + 1 < NCsz) out[row * NCsz + col0 + 1] = acc[r].y + bb.y;
                if (col0 + 2 < NCsz) out[row * NCsz + col0 + 2] = acc[r].z + bb.z;
            }
        }
    }
}

// ---------------- launch ----------------
extern "C" void kernel_launch(void* const* d_in, const int* in_sizes, int n_in,
                              void* d_out, int out_size) {
    const float* x        = (const float*)d_in[0];
    const float* concepts = (const float*)d_in[1];
    const float* lnw      = (const float*)d_in[2];
    const float* lnb      = (const float*)d_in[3];
    const float* fcw      = (const float*)d_in[4];
    const float* fcb      = (const float*)d_in[5];
    const int*   dfi      = (const int*)d_in[6];
    float* out = (float*)d_out;

    const int smem1 = (BM1 + 224) * SA * (int)sizeof(float2);    // 82,944 B (feat aliases it)
    const int smem2 = Ksz * 32 * (int)sizeof(float4)
                    + 32 * SLOTS * (int)sizeof(float2);          // 108,544 B
    cudaFuncSetAttribute(k_main_kernel,
                         cudaFuncAttributeMaxDynamicSharedMemorySize, smem1);
    cudaFuncSetAttribute(k_out_kernel,
                         cudaFuncAttributeMaxDynamicSharedMemorySize, smem2);

    k_rst_kernel<<<1, 32>>>();
    k_norm_kernel<<<Ksz, 256>>>(concepts);
    dim3 trg((NCsz + 31) / 32, (Ksz + 31) / 32);
    k_tr_kernel<<<trg, dim3(32, 8)>>>(fcw);
    k_main_kernel<<<Bsz / BM1, TH1, smem1>>>(x, lnw, lnb, dfi);
    k_fix_kernel<<<120, 256>>>(x, lnw, lnb, dfi);
    dim3 g2(Bsz / RB, (NCsz + TNO - 1) / TNO);
    k_out_kernel<<<g2, 256, smem2>>>(fcb, dfi, out);
}

// round 11
// speedup vs baseline: 1.3112x; 1.1716x over previous
#include <cuda_runtime.h>
#include <math.h>
#include <stdint.h>

// Problem constants (fixed by the dataset instance)
#define Bsz   16384
#define Csz   2048
#define Ksz   200
#define NCsz  1000
#define SLOTS 32
#define GAPEPS 3e-4f

// GEMM1 (tensor) tiling
#define BM1 64
#define TH1 256
#define SA  36        // float2 row stride: 36 mod 16 = 4 -> max 2-way bank conflicts

// GEMM2 tiling
#define TNO 128
#define RB  128

// ---------------- device scratch (no allocations allowed) ----------------
__device__ float g_proto[Ksz * Csz];                    // normalized prototypes
__device__ __align__(16) float g_fcwT[Ksz * NCsz];      // fc_w transposed: [K][NC]
__device__ int   g_sidx[Bsz * SLOTS];                   // per-row surviving indices
__device__ float g_sval[Bsz * SLOTS];                   // per-row surviving LN'd values
__device__ int   g_fix_cnt;                             // # near-tie rows
__device__ int   g_fix_list[Bsz];                       // their row ids

// ---------------- tf32 helpers ----------------
__device__ __forceinline__ float to_tf32(float a) {
    uint32_t r;
    asm("cvt.rna.tf32.f32 %0, %1;" : "=r"(r) : "f"(a));
    return __uint_as_float(r);
}
__device__ __forceinline__ void mma_tf32(float* c,
        uint32_t a0, uint32_t a1, uint32_t a2, uint32_t a3,
        uint32_t b0, uint32_t b1) {
    asm volatile(
        "mma.sync.aligned.m16n8k8.row.col.f32.tf32.tf32.f32 "
        "{%0,%1,%2,%3}, {%4,%5,%6,%7}, {%8,%9}, {%0,%1,%2,%3};"
        : "+f"(c[0]), "+f"(c[1]), "+f"(c[2]), "+f"(c[3])
        : "r"(a0), "r"(a1), "r"(a2), "r"(a3), "r"(b0), "r"(b1));
}

// ---------------- shared LN + top-k select + sparse emit (R3-exact) ----------------
// Returns gap = (19th largest |v|) - (20th largest |v|).
__device__ __forceinline__ float row_select_emit(const float* frow,
        const float* __restrict__ lnw, const float* __restrict__ lnb,
        int ktop, int row, int lane) {
    float f[7];
    float s1 = 0.f;
    #pragma unroll
    for (int j = 0; j < 7; j++) {
        int n = lane + 32 * j;
        float v = (n < Ksz) ? frow[n] : 0.f;
        f[j] = v;
        s1 += v;
    }
    #pragma unroll
    for (int off = 16; off > 0; off >>= 1)
        s1 += __shfl_xor_sync(0xffffffffu, s1, off);
    float mu = s1 / (float)Ksz;
    float s2 = 0.f;
    #pragma unroll
    for (int j = 0; j < 7; j++) {
        int n = lane + 32 * j;
        if (n < Ksz) {
            float d = f[j] - mu;
            s2 = fmaf(d, d, s2);
        }
    }
    #pragma unroll
    for (int off = 16; off > 0; off >>= 1)
        s2 += __shfl_xor_sync(0xffffffffu, s2, off);
    float var  = s2 / (float)Ksz;
    float rstd = 1.f / sqrtf(var + 1e-5f);

    float v[7], av[7], sel[7];
    #pragma unroll
    for (int j = 0; j < 7; j++) {
        int n = lane + 32 * j;
        if (n < Ksz) {
            float z = (f[j] - mu) * rstd * lnw[n] + lnb[n];
            v[j] = z; av[j] = fabsf(z); sel[j] = av[j];
        } else { v[j] = 0.f; av[j] = -1.f; sel[j] = -1.f; }
    }
    float t = 0.f, t19 = 3.4e38f;
    for (int it = 0; it < ktop; it++) {
        float lm = sel[0]; int lj = 0;
        #pragma unroll
        for (int j = 1; j < 7; j++) if (sel[j] > lm) { lm = sel[j]; lj = j; }
        float m = lm;
        #pragma unroll
        for (int off = 16; off > 0; off >>= 1)
            m = fmaxf(m, __shfl_xor_sync(0xffffffffu, m, off));
        unsigned ball = __ballot_sync(0xffffffffu, lm == m);
        int leader = __ffs((int)ball) - 1;
        if (lane == leader) sel[lj] = -2.f;
        if (it == ktop - 2) t19 = m;
        t = m;
    }
    int cnt = 0;
    #pragma unroll
    for (int j = 0; j < 7; j++) {
        bool pred = (av[j] - t > 0.f);
        unsigned msk = __ballot_sync(0xffffffffu, pred);
        if (pred) {
            int pos = cnt + __popc(msk & ((1u << lane) - 1u));
            g_sidx[(size_t)row * SLOTS + pos] = lane + 32 * j;
            g_sval[(size_t)row * SLOTS + pos] = v[j];
        }
        cnt += __popc(msk);
    }
    if (lane == 0) {
        for (int p = cnt; p < ktop; p++) {
            g_sidx[(size_t)row * SLOTS + p] = 0;
            g_sval[(size_t)row * SLOTS + p] = 0.f;
        }
    }
    return t19 - t;
}

// ---------------- reset fixup counter ----------------
__global__ void k_rst_kernel() {
    if (threadIdx.x == 0) g_fix_cnt = 0;
}

// ---------------- normalize prototypes exactly like the reference ----------------
__global__ void k_norm_kernel(const float* __restrict__ concepts) {
    __shared__ float red[256];
    __shared__ float nrm;
    int k = blockIdx.x;
    const float* row = concepts + (size_t)k * Csz;
    float s = 0.f;
    for (int c = threadIdx.x; c < Csz; c += 256) {
        float v = row[c];
        s = fmaf(v, v, s);
    }
    red[threadIdx.x] = s;
    __syncthreads();
    for (int off = 128; off > 0; off >>= 1) {
        if (threadIdx.x < off) red[threadIdx.x] += red[threadIdx.x + off];
        __syncthreads();
    }
    if (threadIdx.x == 0) nrm = fmaxf(sqrtf(red[0]), 1e-12f);
    __syncthreads();
    float n = nrm;
    for (int c = threadIdx.x; c < Csz; c += 256)
        g_proto[(size_t)k * Csz + c] = row[c] / n;
}

// ---------------- tiled transpose fc_w [NC,K] -> [K,NC] ----------------
__global__ void k_tr_kernel(const float* __restrict__ fc_w) {
    __shared__ float tile[32][33];
    const int n0 = blockIdx.x * 32;
    const int k0 = blockIdx.y * 32;
    const int tx = threadIdx.x;
    const int ty = threadIdx.y;
    #pragma unroll
    for (int i = 0; i < 32; i += 8) {
        int n = n0 + ty + i, k = k0 + tx;
        tile[ty + i][tx] = (n < NCsz && k < Ksz) ? fc_w[(size_t)n * Ksz + k] : 0.f;
    }
    __syncthreads();
    #pragma unroll
    for (int i = 0; i < 32; i += 8) {
        int k = k0 + ty + i, n = n0 + tx;
        if (k < Ksz && n < NCsz)
            g_fcwT[(size_t)k * NCsz + n] = tile[tx][ty + i];
    }
}

// ---------------- GEMM1: tf32 3-pass tensor-core + fused LN/top-k ----------------
// Unchanged from round 10 (498us, known rel_err).
__global__ __launch_bounds__(TH1, 2)
void k_main_kernel(const float* __restrict__ x,
                   const float* __restrict__ lnw,
                   const float* __restrict__ lnb,
                   const int*   __restrict__ dfi) {
    extern __shared__ float dyn[];
    float2* sxA  = (float2*)dyn;                 // [64][SA] (hi,lo)
    float2* spB  = sxA + BM1 * SA;               // [224][SA] (hi,lo)
    float*  feat = dyn;                          // [64][200] — aliases tiles (post-mainloop only)

    const int tid  = threadIdx.x;
    const int lane = tid & 31;
    const int wid  = tid >> 5;                   // 0..7
    const int wm   = wid & 1;                    // m block (32 rows)
    const int wn   = wid >> 1;                   // n block (56 cols)
    const int bm0  = blockIdx.x * BM1;

    for (int q = tid; q < 24 * SA; q += TH1)
        spB[200 * SA + q] = make_float2(0.f, 0.f);

    float acc[2][7][4];
    #pragma unroll
    for (int f = 0; f < 2; f++)
        #pragma unroll
        for (int nf = 0; nf < 7; nf++)
            #pragma unroll
            for (int q = 0; q < 4; q++) acc[f][nf][q] = 0.f;

    const int xr = tid >> 2;                     // x-loader row 0..63
    const int xk = (tid & 3) * 8;                // x-loader k offset

    for (int k0 = 0; k0 < Csz; k0 += 32) {
        __syncthreads();
        {
            const float4* p = reinterpret_cast<const float4*>(
                x + (size_t)(bm0 + xr) * Csz + k0 + xk);
            float4 v0 = p[0], v1 = p[1];
            float vv[8] = {v0.x, v0.y, v0.z, v0.w, v1.x, v1.y, v1.z, v1.w};
            #pragma unroll
            for (int i = 0; i < 8; i++) {
                float h = to_tf32(vv[i]);
                float l = to_tf32(vv[i] - h);
                sxA[xr * SA + xk + i] = make_float2(h, l);
            }
        }
        for (int q = tid; q < 200 * 8; q += TH1) {
            int n = q >> 3, kq = (q & 7) * 4;
            float4 v = *reinterpret_cast<const float4*>(
                g_proto + (size_t)n * Csz + k0 + kq);
            float vv[4] = {v.x, v.y, v.z, v.w};
            #pragma unroll
            for (int i = 0; i < 4; i++) {
                float h = to_tf32(vv[i]);
                float l = to_tf32(vv[i] - h);
                spB[n * SA + kq + i] = make_float2(h, l);
            }
        }
        __syncthreads();

        #pragma unroll
        for (int ks = 0; ks < 4; ks++) {
            const int kc = ks * 8 + (lane & 3);
            const int ra = wm * 32 + (lane >> 2);
            float2 Af[2][4];
            #pragma unroll
            for (int f = 0; f < 2; f++) {
                int rb = ra + f * 16;
                Af[f][0] = sxA[rb * SA + kc];
                Af[f][1] = sxA[(rb + 8) * SA + kc];
                Af[f][2] = sxA[rb * SA + kc + 4];
                Af[f][3] = sxA[(rb + 8) * SA + kc + 4];
            }
            #pragma unroll
            for (int nf = 0; nf < 7; nf++) {
                int nn = wn * 56 + nf * 8 + (lane >> 2);
                float2 B0 = spB[nn * SA + kc];
                float2 B1 = spB[nn * SA + kc + 4];
                uint32_t b0h = __float_as_uint(B0.x), b1h = __float_as_uint(B1.x);
                uint32_t b0l = __float_as_uint(B0.y), b1l = __float_as_uint(B1.y);
                #pragma unroll
                for (int f = 0; f < 2; f++) {
                    uint32_t a0h = __float_as_uint(Af[f][0].x);
                    uint32_t a1h = __float_as_uint(Af[f][1].x);
                    uint32_t a2h = __float_as_uint(Af[f][2].x);
                    uint32_t a3h = __float_as_uint(Af[f][3].x);
                    uint32_t a0l = __float_as_uint(Af[f][0].y);
                    uint32_t a1l = __float_as_uint(Af[f][1].y);
                    uint32_t a2l = __float_as_uint(Af[f][2].y);
                    uint32_t a3l = __float_as_uint(Af[f][3].y);
                    mma_tf32(acc[f][nf], a0h, a1h, a2h, a3h, b0h, b1h); // Ah*Bh
                    mma_tf32(acc[f][nf], a0h, a1h, a2h, a3h, b0l, b1l); // Ah*Bl
                    mma_tf32(acc[f][nf], a0l, a1l, a2l, a3l, b0h, b1h); // Al*Bh
                }
            }
        }
    }
    __syncthreads();   // all tile reads done; feat may now alias the tile buffers

    #pragma unroll
    for (int f = 0; f < 2; f++)
        #pragma unroll
        for (int nf = 0; nf < 7; nf++) {
            int row = wm * 32 + f * 16 + (lane >> 2);
            int col = wn * 56 + nf * 8 + 2 * (lane & 3);
            if (col < Ksz) {
                feat[row * Ksz + col]           = acc[f][nf][0];
                feat[row * Ksz + col + 1]       = acc[f][nf][1];
                feat[(row + 8) * Ksz + col]     = acc[f][nf][2];
                feat[(row + 8) * Ksz + col + 1] = acc[f][nf][3];
            }
        }
    __syncthreads();

    const int ktop = Ksz - *dfi;
    for (int rr = 0; rr < 8; rr++) {
        int rloc = wid * 8 + rr;
        int row  = bm0 + rloc;
        float gap = row_select_emit(&feat[rloc * Ksz], lnw, lnb, ktop, row, lane);
        if (lane == 0 && gap < GAPEPS) {
            int p = atomicAdd(&g_fix_cnt, 1);
            g_fix_list[p] = row;
        }
    }
}

// ---------------- fixup v2: coalesced proto staging, R3-exact chain ----------------
// Per flagged row: stage g_proto[:, c:c+32] chunks into smem with coalesced
// float4 reads; thread n accumulates concept n with the EXACT R3 order
// (serial 32-FMA chunk chain, chunk merge). ~12us/row vs ~330us before.
__global__ __launch_bounds__(256, 1)
void k_fix_kernel(const float* __restrict__ x,
                  const float* __restrict__ lnw,
                  const float* __restrict__ lnb,
                  const int*   __restrict__ dfi) {
    __shared__ float xrow[Csz];              // 8 KB
    __shared__ float sp[Ksz * 33];           // 25.8 KB, stride 33 (conflict-free)
    __shared__ float sfeat[224];
    const int tid  = threadIdx.x;
    const int lane = tid & 31;
    const int nfix = g_fix_cnt;
    const int ktop = Ksz - *dfi;

    for (int i = blockIdx.x; i < nfix; i += gridDim.x) {
        int row = g_fix_list[i];
        __syncthreads();
        for (int q = tid; q < Csz / 4; q += 256)
            *reinterpret_cast<float4*>(&xrow[q * 4]) =
                *reinterpret_cast<const float4*>(&x[(size_t)row * Csz + q * 4]);

        float a = 0.f;
        for (int c = 0; c < Csz; c += 32) {
            __syncthreads();
            // stage proto[:,c:c+32]: coalesced float4 global reads
            for (int q = tid; q < Ksz * 8; q += 256) {
                int n = q >> 3, f4 = (q & 7) * 4;
                float4 v = *reinterpret_cast<const float4*>(
                    &g_proto[(size_t)n * Csz + c + f4]);
                float* d = &sp[n * 33 + f4];
                d[0] = v.x; d[1] = v.y; d[2] = v.z; d[3] = v.w;
            }
            __syncthreads();
            if (tid < Ksz) {
                float aT = 0.f;
                #pragma unroll
                for (int kk = 0; kk < 32; kk++)
                    aT = fmaf(xrow[c + kk], sp[tid * 33 + kk], aT);  // R3 chunk chain
                a += aT;                                              // R3 chunk merge
            }
        }
        if (tid < Ksz) sfeat[tid] = a;
        __syncthreads();
        if (tid < 32)
            row_select_emit(sfeat, lnw, lnb, ktop, row, lane);
    }
}

// ---------------- sparse GEMM2 v4 (round-6 winner, unchanged) ----------------
__global__ __launch_bounds__(256, 2)
void k_out_kernel(const float* __restrict__ fcb,
                  const int*   __restrict__ dfi,
                  float* __restrict__ out) {
    extern __shared__ float4 ws4[];                 // [Ksz][32] float4 = 100KB
    float2* pk = (float2*)(ws4 + Ksz * 32);         // [32][SLOTS] packed (val, idx)

    const int tid  = threadIdx.x;
    const int lane = tid & 31;
    const int wid  = tid >> 5;
    const int cb   = blockIdx.y;
    const int col0 = cb * TNO + lane * 4;
    const bool vall = (col0 + 3) < NCsz;

    for (int q = tid; q < Ksz * 32; q += 256) {
        int k = q >> 5, t4 = q & 31;
        int c = cb * TNO + t4 * 4;
        float4 w;
        if (c + 3 < NCsz) {
            w = *reinterpret_cast<const float4*>(&g_fcwT[(size_t)k * NCsz + c]);
        } else {
            w.x = (c + 0 < NCsz) ? g_fcwT[(size_t)k * NCsz + c + 0] : 0.f;
            w.y = (c + 1 < NCsz) ? g_fcwT[(size_t)k * NCsz + c + 1] : 0.f;
            w.z = (c + 2 < NCsz) ? g_fcwT[(size_t)k * NCsz + c + 2] : 0.f;
            w.w = 0.f;
        }
        ws4[q] = w;
    }

    float4 bb;
    bb.x = (col0 + 0 < NCsz) ? fcb[col0 + 0] : 0.f;
    bb.y = (col0 + 1 < NCsz) ? fcb[col0 + 1] : 0.f;
    bb.z = (col0 + 2 < NCsz) ? fcb[col0 + 2] : 0.f;
    bb.w = (col0 + 3 < NCsz) ? fcb[col0 + 3] : 0.f;
    const int ktop = Ksz - *dfi;
    const int r0   = blockIdx.x * RB;

    for (int batch = 0; batch < RB; batch += 32) {
        __syncthreads();
        for (int q = tid; q < 32 * ktop; q += 256) {
            int r = q / ktop, j = q - r * ktop;
            size_t g = (size_t)(r0 + batch + r) * SLOTS + j;
            pk[r * SLOTS + j] = make_float2(g_sval[g], __int_as_float(g_sidx[g]));
        }
        __syncthreads();

        float4 acc[4];
        #pragma unroll
        for (int r = 0; r < 4; r++) acc[r] = make_float4(0.f, 0.f, 0.f, 0.f);
        const float2* pkr = pk + (wid * 4) * SLOTS;
        #pragma unroll 5
        for (int j = 0; j < ktop; j++) {
            #pragma unroll
            for (int r = 0; r < 4; r++) {
                float2 p = pkr[r * SLOTS + j];
                int idx  = __float_as_int(p.y);
                float4 w = ws4[idx * 32 + lane];
                acc[r].x = fmaf(p.x, w.x, acc[r].x);
                acc[r].y = fmaf(p.x, w.y, acc[r].y);
                acc[r].z = fmaf(p.x, w.z, acc[r].z);
                acc[r].w = fmaf(p.x, w.w, acc[r].w);
            }
        }
        #pragma unroll
        for (int r = 0; r < 4; r++) {
            size_t row = (size_t)(r0 + batch + wid * 4 + r);
            if (vall) {
                float4 o = make_float4(acc[r].x + bb.x, acc[r].y + bb.y,
                                       acc[r].z + bb.z, acc[r].w + bb.w);
                *reinterpret_cast<float4*>(&out[row * NCsz + col0]) = o;
            } else {
                if (col0 + 0 < NCsz) out[row * NCsz + col0 + 0] = acc[r].x + bb.x;
                if (col0 + 1 < NCsz) out[row * NCsz + col0 + 1] = acc[r].y + bb.y;
                if (col0 + 2 < NCsz) out[row * NCsz + col0 + 2] = acc[r].z + bb.z;
            }
        }
    }
}

// ---------------- launch ----------------
extern "C" void kernel_launch(void* const* d_in, const int* in_sizes, int n_in,
                              void* d_out, int out_size) {
    const float* x        = (const float*)d_in[0];
    const float* concepts = (const float*)d_in[1];
    const float* lnw      = (const float*)d_in[2];
    const float* lnb      = (const float*)d_in[3];
    const float* fcw      = (const float*)d_in[4];
    const float* fcb      = (const float*)d_in[5];
    const int*   dfi      = (const int*)d_in[6];
    float* out = (float*)d_out;

    const int smem1 = (BM1 + 224) * SA * (int)sizeof(float2);    // 82,944 B (feat aliases it)
    const int smem2 = Ksz * 32 * (int)sizeof(float4)
                    + 32 * SLOTS * (int)sizeof(float2);          // 108,544 B
    cudaFuncSetAttribute(k_main_kernel,
                         cudaFuncAttributeMaxDynamicSharedMemorySize, smem1);
    cudaFuncSetAttribute(k_out_kernel,
                         cudaFuncAttributeMaxDynamicSharedMemorySize, smem2);

    k_rst_kernel<<<1, 32>>>();
    k_norm_kernel<<<Ksz, 256>>>(concepts);
    dim3 trg((NCsz + 31) / 32, (Ksz + 31) / 32);
    k_tr_kernel<<<trg, dim3(32, 8)>>>(fcw);
    k_main_kernel<<<Bsz / BM1, TH1, smem1>>>(x, lnw, lnb, dfi);
    k_fix_kernel<<<120, 256>>>(x, lnw, lnb, dfi);
    dim3 g2(Bsz / RB, (NCsz + TNO - 1) / TNO);
    k_out_kernel<<<g2, 256, smem2>>>(fcb, dfi, out);
}

// round 12
// speedup vs baseline: 1.4004x; 1.0681x over previous
#include <cuda_runtime.h>
#include <math.h>
#include <stdint.h>

// Problem constants (fixed by the dataset instance)
#define Bsz   16384
#define Csz   2048
#define Ksz   200
#define NCsz  1000
#define SLOTS 32
#define GAPEPS 3e-4f

// GEMM1 (tensor) tiling
#define BM1 64
#define TH1 256
#define SA  36        // float2 row stride: 36 mod 16 = 4 -> max 2-way bank conflicts

// GEMM2 tiling
#define TNO 128
#define RB  128

// ---------------- device scratch (no allocations allowed) ----------------
__device__ float g_proto[Ksz * Csz];                    // normalized prototypes (fp32)
__device__ __align__(16) float2 g_protoHL[Ksz * Csz];   // precomputed (hi,lo) tf32 split
__device__ __align__(16) float g_fcwT[Ksz * NCsz];      // fc_w transposed: [K][NC]
__device__ int   g_sidx[Bsz * SLOTS];                   // per-row surviving indices
__device__ float g_sval[Bsz * SLOTS];                   // per-row surviving LN'd values
__device__ int   g_fix_cnt;                             // # near-tie rows
__device__ int   g_fix_list[Bsz];                       // their row ids

// ---------------- tf32 helpers ----------------
__device__ __forceinline__ float to_tf32(float a) {
    uint32_t r;
    asm("cvt.rna.tf32.f32 %0, %1;" : "=r"(r) : "f"(a));
    return __uint_as_float(r);
}
__device__ __forceinline__ void mma_tf32(float* c,
        uint32_t a0, uint32_t a1, uint32_t a2, uint32_t a3,
        uint32_t b0, uint32_t b1) {
    asm volatile(
        "mma.sync.aligned.m16n8k8.row.col.f32.tf32.tf32.f32 "
        "{%0,%1,%2,%3}, {%4,%5,%6,%7}, {%8,%9}, {%0,%1,%2,%3};"
        : "+f"(c[0]), "+f"(c[1]), "+f"(c[2]), "+f"(c[3])
        : "r"(a0), "r"(a1), "r"(a2), "r"(a3), "r"(b0), "r"(b1));
}

// ---------------- shared LN + top-k select + sparse emit (R3-exact) ----------------
// Returns gap = (19th largest |v|) - (20th largest |v|).
__device__ __forceinline__ float row_select_emit(const float* frow,
        const float* __restrict__ lnw, const float* __restrict__ lnb,
        int ktop, int row, int lane) {
    float f[7];
    float s1 = 0.f;
    #pragma unroll
    for (int j = 0; j < 7; j++) {
        int n = lane + 32 * j;
        float v = (n < Ksz) ? frow[n] : 0.f;
        f[j] = v;
        s1 += v;
    }
    #pragma unroll
    for (int off = 16; off > 0; off >>= 1)
        s1 += __shfl_xor_sync(0xffffffffu, s1, off);
    float mu = s1 / (float)Ksz;
    float s2 = 0.f;
    #pragma unroll
    for (int j = 0; j < 7; j++) {
        int n = lane + 32 * j;
        if (n < Ksz) {
            float d = f[j] - mu;
            s2 = fmaf(d, d, s2);
        }
    }
    #pragma unroll
    for (int off = 16; off > 0; off >>= 1)
        s2 += __shfl_xor_sync(0xffffffffu, s2, off);
    float var  = s2 / (float)Ksz;
    float rstd = 1.f / sqrtf(var + 1e-5f);

    float v[7], av[7], sel[7];
    #pragma unroll
    for (int j = 0; j < 7; j++) {
        int n = lane + 32 * j;
        if (n < Ksz) {
            float z = (f[j] - mu) * rstd * lnw[n] + lnb[n];
            v[j] = z; av[j] = fabsf(z); sel[j] = av[j];
        } else { v[j] = 0.f; av[j] = -1.f; sel[j] = -1.f; }
    }
    float t = 0.f, t19 = 3.4e38f;
    for (int it = 0; it < ktop; it++) {
        float lm = sel[0]; int lj = 0;
        #pragma unroll
        for (int j = 1; j < 7; j++) if (sel[j] > lm) { lm = sel[j]; lj = j; }
        float m = lm;
        #pragma unroll
        for (int off = 16; off > 0; off >>= 1)
            m = fmaxf(m, __shfl_xor_sync(0xffffffffu, m, off));
        unsigned ball = __ballot_sync(0xffffffffu, lm == m);
        int leader = __ffs((int)ball) - 1;
        if (lane == leader) sel[lj] = -2.f;
        if (it == ktop - 2) t19 = m;
        t = m;
    }
    int cnt = 0;
    #pragma unroll
    for (int j = 0; j < 7; j++) {
        bool pred = (av[j] - t > 0.f);
        unsigned msk = __ballot_sync(0xffffffffu, pred);
        if (pred) {
            int pos = cnt + __popc(msk & ((1u << lane) - 1u));
            g_sidx[(size_t)row * SLOTS + pos] = lane + 32 * j;
            g_sval[(size_t)row * SLOTS + pos] = v[j];
        }
        cnt += __popc(msk);
    }
    if (lane == 0) {
        for (int p = cnt; p < ktop; p++) {
            g_sidx[(size_t)row * SLOTS + p] = 0;
            g_sval[(size_t)row * SLOTS + p] = 0.f;
        }
    }
    return t19 - t;
}

// ---------------- reset fixup counter ----------------
__global__ void k_rst_kernel() {
    if (threadIdx.x == 0) g_fix_cnt = 0;
}

// ---------------- normalize prototypes exactly like the reference ----------------
__global__ void k_norm_kernel(const float* __restrict__ concepts) {
    __shared__ float red[256];
    __shared__ float nrm;
    int k = blockIdx.x;
    const float* row = concepts + (size_t)k * Csz;
    float s = 0.f;
    for (int c = threadIdx.x; c < Csz; c += 256) {
        float v = row[c];
        s = fmaf(v, v, s);
    }
    red[threadIdx.x] = s;
    __syncthreads();
    for (int off = 128; off > 0; off >>= 1) {
        if (threadIdx.x < off) red[threadIdx.x] += red[threadIdx.x + off];
        __syncthreads();
    }
    if (threadIdx.x == 0) nrm = fmaxf(sqrtf(red[0]), 1e-12f);
    __syncthreads();
    float n = nrm;
    for (int c = threadIdx.x; c < Csz; c += 256)
        g_proto[(size_t)k * Csz + c] = row[c] / n;
}

// ---------------- precompute (hi,lo) tf32 split of prototypes (once) ----------------
// Same cvt ops as the old in-kernel split -> bit-identical hi/lo values.
__global__ void k_split_kernel() {
    int k = blockIdx.x;
    for (int c = threadIdx.x; c < Csz; c += 256) {
        float v = g_proto[(size_t)k * Csz + c];
        float h = to_tf32(v);
        float l = to_tf32(v - h);
        g_protoHL[(size_t)k * Csz + c] = make_float2(h, l);
    }
}

// ---------------- tiled transpose fc_w [NC,K] -> [K,NC] ----------------
__global__ void k_tr_kernel(const float* __restrict__ fc_w) {
    __shared__ float tile[32][33];
    const int n0 = blockIdx.x * 32;
    const int k0 = blockIdx.y * 32;
    const int tx = threadIdx.x;
    const int ty = threadIdx.y;
    #pragma unroll
    for (int i = 0; i < 32; i += 8) {
        int n = n0 + ty + i, k = k0 + tx;
        tile[ty + i][tx] = (n < NCsz && k < Ksz) ? fc_w[(size_t)n * Ksz + k] : 0.f;
    }
    __syncthreads();
    #pragma unroll
    for (int i = 0; i < 32; i += 8) {
        int k = k0 + ty + i, n = n0 + tx;
        if (k < Ksz && n < NCsz)
            g_fcwT[(size_t)k * NCsz + n] = tile[tx][ty + i];
    }
}

// ---------------- GEMM1: tf32 3-pass tensor-core + fused LN/top-k ----------------
// Same mma sequence as rounds 9-11; proto staging is now a pure float4 copy
// from the precomputed g_protoHL (no per-tile cvt ALU work).
__global__ __launch_bounds__(TH1, 2)
void k_main_kernel(const float* __restrict__ x,
                   const float* __restrict__ lnw,
                   const float* __restrict__ lnb,
                   const int*   __restrict__ dfi) {
    extern __shared__ float dyn[];
    float2* sxA  = (float2*)dyn;                 // [64][SA] (hi,lo)
    float2* spB  = sxA + BM1 * SA;               // [224][SA] (hi,lo)
    float*  feat = dyn;                          // [64][200] — aliases tiles (post-mainloop only)

    const int tid  = threadIdx.x;
    const int lane = tid & 31;
    const int wid  = tid >> 5;                   // 0..7
    const int wm   = wid & 1;                    // m block (32 rows)
    const int wn   = wid >> 1;                   // n block (56 cols)
    const int bm0  = blockIdx.x * BM1;

    for (int q = tid; q < 24 * SA; q += TH1)
        spB[200 * SA + q] = make_float2(0.f, 0.f);

    float acc[2][7][4];
    #pragma unroll
    for (int f = 0; f < 2; f++)
        #pragma unroll
        for (int nf = 0; nf < 7; nf++)
            #pragma unroll
            for (int q = 0; q < 4; q++) acc[f][nf][q] = 0.f;

    const int xr = tid >> 2;                     // x-loader row 0..63
    const int xk = (tid & 3) * 8;                // x-loader k offset

    for (int k0 = 0; k0 < Csz; k0 += 32) {
        __syncthreads();
        // x tile: 64x32, split hi/lo inline (each x element converted once chip-wide)
        {
            const float4* p = reinterpret_cast<const float4*>(
                x + (size_t)(bm0 + xr) * Csz + k0 + xk);
            float4 v0 = p[0], v1 = p[1];
            float vv[8] = {v0.x, v0.y, v0.z, v0.w, v1.x, v1.y, v1.z, v1.w};
            #pragma unroll
            for (int i = 0; i < 8; i++) {
                float h = to_tf32(vv[i]);
                float l = to_tf32(vv[i] - h);
                sxA[xr * SA + xk + i] = make_float2(h, l);
            }
        }
        // proto tile: pure float4 copy of precomputed (hi,lo) pairs
        for (int q = tid; q < Ksz * 16; q += TH1) {
            int n  = q >> 4;
            int kq = (q & 15) * 2;               // k offset (2 pairs per float4)
            float4 v = *reinterpret_cast<const float4*>(
                &g_protoHL[(size_t)n * Csz + k0 + kq]);
            *reinterpret_cast<float4*>(&spB[n * SA + kq]) = v;
        }
        __syncthreads();

        #pragma unroll
        for (int ks = 0; ks < 4; ks++) {
            const int kc = ks * 8 + (lane & 3);
            const int ra = wm * 32 + (lane >> 2);
            float2 Af[2][4];
            #pragma unroll
            for (int f = 0; f < 2; f++) {
                int rb = ra + f * 16;
                Af[f][0] = sxA[rb * SA + kc];
                Af[f][1] = sxA[(rb + 8) * SA + kc];
                Af[f][2] = sxA[rb * SA + kc + 4];
                Af[f][3] = sxA[(rb + 8) * SA + kc + 4];
            }
            #pragma unroll
            for (int nf = 0; nf < 7; nf++) {
                int nn = wn * 56 + nf * 8 + (lane >> 2);
                float2 B0 = spB[nn * SA + kc];
                float2 B1 = spB[nn * SA + kc + 4];
                uint32_t b0h = __float_as_uint(B0.x), b1h = __float_as_uint(B1.x);
                uint32_t b0l = __float_as_uint(B0.y), b1l = __float_as_uint(B1.y);
                #pragma unroll
                for (int f = 0; f < 2; f++) {
                    uint32_t a0h = __float_as_uint(Af[f][0].x);
                    uint32_t a1h = __float_as_uint(Af[f][1].x);
                    uint32_t a2h = __float_as_uint(Af[f][2].x);
                    uint32_t a3h = __float_as_uint(Af[f][3].x);
                    uint32_t a0l = __float_as_uint(Af[f][0].y);
                    uint32_t a1l = __float_as_uint(Af[f][1].y);
                    uint32_t a2l = __float_as_uint(Af[f][2].y);
                    uint32_t a3l = __float_as_uint(Af[f][3].y);
                    mma_tf32(acc[f][nf], a0h, a1h, a2h, a3h, b0h, b1h); // Ah*Bh
                    mma_tf32(acc[f][nf], a0h, a1h, a2h, a3h, b0l, b1l); // Ah*Bl
                    mma_tf32(acc[f][nf], a0l, a1l, a2l, a3l, b0h, b1h); // Al*Bh
                }
            }
        }
    }
    __syncthreads();   // all tile reads done; feat may now alias the tile buffers

    #pragma unroll
    for (int f = 0; f < 2; f++)
        #pragma unroll
        for (int nf = 0; nf < 7; nf++) {
            int row = wm * 32 + f * 16 + (lane >> 2);
            int col = wn * 56 + nf * 8 + 2 * (lane & 3);
            if (col < Ksz) {
                feat[row * Ksz + col]           = acc[f][nf][0];
                feat[row * Ksz + col + 1]       = acc[f][nf][1];
                feat[(row + 8) * Ksz + col]     = acc[f][nf][2];
                feat[(row + 8) * Ksz + col + 1] = acc[f][nf][3];
            }
        }
    __syncthreads();

    const int ktop = Ksz - *dfi;
    for (int rr = 0; rr < 8; rr++) {
        int rloc = wid * 8 + rr;
        int row  = bm0 + rloc;
        float gap = row_select_emit(&feat[rloc * Ksz], lnw, lnb, ktop, row, lane);
        if (lane == 0 && gap < GAPEPS) {
            int p = atomicAdd(&g_fix_cnt, 1);
            g_fix_list[p] = row;
        }
    }
}

// ---------------- fixup v3: 4 rows/block, shared proto staging, R3-exact ----------------
// Per 4-row group: stage each proto chunk once; run 4 independent R3-exact
// chains (same per-row op order as rounds 3-11 -> bit-identical results).
__global__ __launch_bounds__(256, 1)
void k_fix_kernel(const float* __restrict__ x,
                  const float* __restrict__ lnw,
                  const float* __restrict__ lnb,
                  const int*   __restrict__ dfi) {
    extern __shared__ float fsm[];
    float* xr4 = fsm;                        // [4][2048]   32 KB
    float* sp  = fsm + 4 * Csz;              // [200*33]    26.4 KB
    float* sf  = sp + Ksz * 33;              // [4][224]    3.6 KB
    const int tid  = threadIdx.x;
    const int lane = tid & 31;
    const int nfix = g_fix_cnt;
    const int ktop = Ksz - *dfi;

    for (int base = blockIdx.x * 4; base < nfix; base += gridDim.x * 4) {
        const int nr = (nfix - base < 4) ? (nfix - base) : 4;
        __syncthreads();
        for (int r = 0; r < nr; r++) {
            int row = g_fix_list[base + r];
            for (int q = tid; q < Csz / 4; q += 256)
                reinterpret_cast<float4*>(&xr4[r * Csz])[q] =
                    reinterpret_cast<const float4*>(&x[(size_t)row * Csz])[q];
        }

        float a[4] = {0.f, 0.f, 0.f, 0.f};
        for (int c = 0; c < Csz; c += 32) {
            __syncthreads();
            for (int q = tid; q < Ksz * 8; q += 256) {
                int n = q >> 3, f4 = (q & 7) * 4;
                float4 v = *reinterpret_cast<const float4*>(
                    &g_proto[(size_t)n * Csz + c + f4]);
                float* d = &sp[n * 33 + f4];
                d[0] = v.x; d[1] = v.y; d[2] = v.z; d[3] = v.w;
            }
            __syncthreads();
            if (tid < Ksz) {
                float aT[4] = {0.f, 0.f, 0.f, 0.f};
                #pragma unroll
                for (int kk = 0; kk < 32; kk++) {
                    float s = sp[tid * 33 + kk];
                    #pragma unroll
                    for (int r = 0; r < 4; r++)
                        aT[r] = fmaf(xr4[r * Csz + c + kk], s, aT[r]); // R3 chunk chain
                }
                #pragma unroll
                for (int r = 0; r < 4; r++) a[r] += aT[r];             // R3 chunk merge
            }
        }
        if (tid < Ksz) {
            #pragma unroll
            for (int r = 0; r < 4; r++) sf[r * 224 + tid] = a[r];
        }
        __syncthreads();
        if (tid < 32) {
            for (int r = 0; r < nr; r++) {
                int row = g_fix_list[base + r];
                row_select_emit(&sf[r * 224], lnw, lnb, ktop, row, lane);
            }
        }
    }
}

// ---------------- sparse GEMM2 v4 (round-6 winner, unchanged) ----------------
__global__ __launch_bounds__(256, 2)
void k_out_kernel(const float* __restrict__ fcb,
                  const int*   __restrict__ dfi,
                  float* __restrict__ out) {
    extern __shared__ float4 ws4[];                 // [Ksz][32] float4 = 100KB
    float2* pk = (float2*)(ws4 + Ksz * 32);         // [32][SLOTS] packed (val, idx)

    const int tid  = threadIdx.x;
    const int lane = tid & 31;
    const int wid  = tid >> 5;
    const int cb   = blockIdx.y;
    const int col0 = cb * TNO + lane * 4;
    const bool vall = (col0 + 3) < NCsz;

    for (int q = tid; q < Ksz * 32; q += 256) {
        int k = q >> 5, t4 = q & 31;
        int c = cb * TNO + t4 * 4;
        float4 w;
        if (c + 3 < NCsz) {
            w = *reinterpret_cast<const float4*>(&g_fcwT[(size_t)k * NCsz + c]);
        } else {
            w.x = (c + 0 < NCsz) ? g_fcwT[(size_t)k * NCsz + c + 0] : 0.f;
            w.y = (c + 1 < NCsz) ? g_fcwT[(size_t)k * NCsz + c + 1] : 0.f;
            w.z = (c + 2 < NCsz) ? g_fcwT[(size_t)k * NCsz + c + 2] : 0.f;
            w.w = 0.f;
        }
        ws4[q] = w;
    }

    float4 bb;
    bb.x = (col0 + 0 < NCsz) ? fcb[col0 + 0] : 0.f;
    bb.y = (col0 + 1 < NCsz) ? fcb[col0 + 1] : 0.f;
    bb.z = (col0 + 2 < NCsz) ? fcb[col0 + 2] : 0.f;
    bb.w = (col0 + 3 < NCsz) ? fcb[col0 + 3] : 0.f;
    const int ktop = Ksz - *dfi;
    const int r0   = blockIdx.x * RB;

    for (int batch = 0; batch < RB; batch += 32) {
        __syncthreads();
        for (int q = tid; q < 32 * ktop; q += 256) {
            int r = q / ktop, j = q - r * ktop;
            size_t g = (size_t)(r0 + batch + r) * SLOTS + j;
            pk[r * SLOTS + j] = make_float2(g_sval[g], __int_as_float(g_sidx[g]));
        }
        __syncthreads();

        float4 acc[4];
        #pragma unroll
        for (int r = 0; r < 4; r++) acc[r] = make_float4(0.f, 0.f, 0.f, 0.f);
        const float2* pkr = pk + (wid * 4) * SLOTS;
        #pragma unroll 5
        for (int j = 0; j < ktop; j++) {
            #pragma unroll
            for (int r = 0; r < 4; r++) {
                float2 p = pkr[r * SLOTS + j];
                int idx  = __float_as_int(p.y);
                float4 w = ws4[idx * 32 + lane];
                acc[r].x = fmaf(p.x, w.x, acc[r].x);
                acc[r].y = fmaf(p.x, w.y, acc[r].y);
                acc[r].z = fmaf(p.x, w.z, acc[r].z);
                acc[r].w = fmaf(p.x, w.w, acc[r].w);
            }
        }
        #pragma unroll
        for (int r = 0; r < 4; r++) {
            size_t row = (size_t)(r0 + batch + wid * 4 + r);
            if (vall) {
                float4 o = make_float4(acc[r].x + bb.x, acc[r].y + bb.y,
                                       acc[r].z + bb.z, acc[r].w + bb.w);
                *reinterpret_cast<float4*>(&out[row * NCsz + col0]) = o;
            } else {
                if (col0 + 0 < NCsz) out[row * NCsz + col0 + 0] = acc[r].x + bb.x;
                if (col0 + 1 < NCsz) out[row * NCsz + col0 + 1] = acc[r].y + bb.y;
                if (col0 + 2 < NCsz) out[row * NCsz + col0 + 2] = acc[r].z + bb.z;
            }
        }
    }
}

// ---------------- launch ----------------
extern "C" void kernel_launch(void* const* d_in, const int* in_sizes, int n_in,
                              void* d_out, int out_size) {
    const float* x        = (const float*)d_in[0];
    const float* concepts = (const float*)d_in[1];
    const float* lnw      = (const float*)d_in[2];
    const float* lnb      = (const float*)d_in[3];
    const float* fcw      = (const float*)d_in[4];
    const float* fcb      = (const float*)d_in[5];
    const int*   dfi      = (const int*)d_in[6];
    float* out = (float*)d_out;

    const int smem1 = (BM1 + 224) * SA * (int)sizeof(float2);    // 82,944 B
    const int smem2 = Ksz * 32 * (int)sizeof(float4)
                    + 32 * SLOTS * (int)sizeof(float2);          // 108,544 B
    const int smemF = (4 * Csz + Ksz * 33 + 4 * 224) * (int)sizeof(float); // 62,752 B
    cudaFuncSetAttribute(k_main_kernel,
                         cudaFuncAttributeMaxDynamicSharedMemorySize, smem1);
    cudaFuncSetAttribute(k_out_kernel,
                         cudaFuncAttributeMaxDynamicSharedMemorySize, smem2);
    cudaFuncSetAttribute(k_fix_kernel,
                         cudaFuncAttributeMaxDynamicSharedMemorySize, smemF);

    k_rst_kernel<<<1, 32>>>();
    k_norm_kernel<<<Ksz, 256>>>(concepts);
    k_split_kernel<<<Ksz, 256>>>();
    dim3 trg((NCsz + 31) / 32, (Ksz + 31) / 32);
    k_tr_kernel<<<trg, dim3(32, 8)>>>(fcw);
    k_main_kernel<<<Bsz / BM1, TH1, smem1>>>(x, lnw, lnb, dfi);
    k_fix_kernel<<<256, 256, smemF>>>(x, lnw, lnb, dfi);
    dim3 g2(Bsz / RB, (NCsz + TNO - 1) / TNO);
    k_out_kernel<<<g2, 256, smem2>>>(fcb, dfi, out);
}

// round 13
// speedup vs baseline: 1.4325x; 1.0229x over previous
#include <cuda_runtime.h>
#include <math.h>
#include <stdint.h>

// Problem constants (fixed by the dataset instance)
#define Bsz   16384
#define Csz   2048
#define Ksz   200
#define NCsz  1000
#define SLOTS 32
#define GAPEPS 3e-4f

// GEMM1 (tensor) tiling
#define BM1 64
#define TH1 256
#define SA  36        // float2 row stride: 36 mod 16 = 4 -> max 2-way bank conflicts

// GEMM2 tiling
#define TNO 128
#define RB  128

// ---------------- device scratch (no allocations allowed) ----------------
__device__ float g_proto[Ksz * Csz];                    // normalized prototypes (fp32)
__device__ __align__(16) float g_fcwT[Ksz * NCsz];      // fc_w transposed: [K][NC]
__device__ int   g_sidx[Bsz * SLOTS];                   // per-row surviving indices
__device__ float g_sval[Bsz * SLOTS];                   // per-row surviving LN'd values
__device__ int   g_fix_cnt;                             // # near-tie rows
__device__ int   g_fix_list[Bsz];                       // their row ids

// ---------------- tf32 helpers ----------------
__device__ __forceinline__ float to_tf32(float a) {
    uint32_t r;
    asm("cvt.rna.tf32.f32 %0, %1;" : "=r"(r) : "f"(a));
    return __uint_as_float(r);
}
__device__ __forceinline__ void mma_tf32(float* c,
        uint32_t a0, uint32_t a1, uint32_t a2, uint32_t a3,
        uint32_t b0, uint32_t b1) {
    asm volatile(
        "mma.sync.aligned.m16n8k8.row.col.f32.tf32.tf32.f32 "
        "{%0,%1,%2,%3}, {%4,%5,%6,%7}, {%8,%9}, {%0,%1,%2,%3};"
        : "+f"(c[0]), "+f"(c[1]), "+f"(c[2]), "+f"(c[3])
        : "r"(a0), "r"(a1), "r"(a2), "r"(a3), "r"(b0), "r"(b1));
}

// ---------------- shared LN + top-k select + sparse emit (R3-exact) ----------------
// Returns gap = (19th largest |v|) - (20th largest |v|).
__device__ __forceinline__ float row_select_emit(const float* frow,
        const float* __restrict__ lnw, const float* __restrict__ lnb,
        int ktop, int row, int lane) {
    float f[7];
    float s1 = 0.f;
    #pragma unroll
    for (int j = 0; j < 7; j++) {
        int n = lane + 32 * j;
        float v = (n < Ksz) ? frow[n] : 0.f;
        f[j] = v;
        s1 += v;
    }
    #pragma unroll
    for (int off = 16; off > 0; off >>= 1)
        s1 += __shfl_xor_sync(0xffffffffu, s1, off);
    float mu = s1 / (float)Ksz;
    float s2 = 0.f;
    #pragma unroll
    for (int j = 0; j < 7; j++) {
        int n = lane + 32 * j;
        if (n < Ksz) {
            float d = f[j] - mu;
            s2 = fmaf(d, d, s2);
        }
    }
    #pragma unroll
    for (int off = 16; off > 0; off >>= 1)
        s2 += __shfl_xor_sync(0xffffffffu, s2, off);
    float var  = s2 / (float)Ksz;
    float rstd = 1.f / sqrtf(var + 1e-5f);

    float v[7], av[7], sel[7];
    #pragma unroll
    for (int j = 0; j < 7; j++) {
        int n = lane + 32 * j;
        if (n < Ksz) {
            float z = (f[j] - mu) * rstd * lnw[n] + lnb[n];
            v[j] = z; av[j] = fabsf(z); sel[j] = av[j];
        } else { v[j] = 0.f; av[j] = -1.f; sel[j] = -1.f; }
    }
    float t = 0.f, t19 = 3.4e38f;
    for (int it = 0; it < ktop; it++) {
        float lm = sel[0]; int lj = 0;
        #pragma unroll
        for (int j = 1; j < 7; j++) if (sel[j] > lm) { lm = sel[j]; lj = j; }
        float m = lm;
        #pragma unroll
        for (int off = 16; off > 0; off >>= 1)
            m = fmaxf(m, __shfl_xor_sync(0xffffffffu, m, off));
        unsigned ball = __ballot_sync(0xffffffffu, lm == m);
        int leader = __ffs((int)ball) - 1;
        if (lane == leader) sel[lj] = -2.f;
        if (it == ktop - 2) t19 = m;
        t = m;
    }
    int cnt = 0;
    #pragma unroll
    for (int j = 0; j < 7; j++) {
        bool pred = (av[j] - t > 0.f);
        unsigned msk = __ballot_sync(0xffffffffu, pred);
        if (pred) {
            int pos = cnt + __popc(msk & ((1u << lane) - 1u));
            g_sidx[(size_t)row * SLOTS + pos] = lane + 32 * j;
            g_sval[(size_t)row * SLOTS + pos] = v[j];
        }
        cnt += __popc(msk);
    }
    if (lane == 0) {
        for (int p = cnt; p < ktop; p++) {
            g_sidx[(size_t)row * SLOTS + p] = 0;
            g_sval[(size_t)row * SLOTS + p] = 0.f;
        }
    }
    return t19 - t;
}

// ---------------- reset fixup counter ----------------
__global__ void k_rst_kernel() {
    if (threadIdx.x == 0) g_fix_cnt = 0;
}

// ---------------- normalize prototypes exactly like the reference ----------------
__global__ void k_norm_kernel(const float* __restrict__ concepts) {
    __shared__ float red[256];
    __shared__ float nrm;
    int k = blockIdx.x;
    const float* row = concepts + (size_t)k * Csz;
    float s = 0.f;
    for (int c = threadIdx.x; c < Csz; c += 256) {
        float v = row[c];
        s = fmaf(v, v, s);
    }
    red[threadIdx.x] = s;
    __syncthreads();
    for (int off = 128; off > 0; off >>= 1) {
        if (threadIdx.x < off) red[threadIdx.x] += red[threadIdx.x + off];
        __syncthreads();
    }
    if (threadIdx.x == 0) nrm = fmaxf(sqrtf(red[0]), 1e-12f);
    __syncthreads();
    float n = nrm;
    for (int c = threadIdx.x; c < Csz; c += 256)
        g_proto[(size_t)k * Csz + c] = row[c] / n;
}

// ---------------- tiled transpose fc_w [NC,K] -> [K,NC] ----------------
__global__ void k_tr_kernel(const float* __restrict__ fc_w) {
    __shared__ float tile[32][33];
    const int n0 = blockIdx.x * 32;
    const int k0 = blockIdx.y * 32;
    const int tx = threadIdx.x;
    const int ty = threadIdx.y;
    #pragma unroll
    for (int i = 0; i < 32; i += 8) {
        int n = n0 + ty + i, k = k0 + tx;
        tile[ty + i][tx] = (n < NCsz && k < Ksz) ? fc_w[(size_t)n * Ksz + k] : 0.f;
    }
    __syncthreads();
    #pragma unroll
    for (int i = 0; i < 32; i += 8) {
        int k = k0 + ty + i, n = n0 + tx;
        if (k < Ksz && n < NCsz)
            g_fcwT[(size_t)k * NCsz + n] = tile[tx][ty + i];
    }
}

// ---------------- GEMM1: tf32 3-pass tensor-core + fused LN/top-k ----------------
// EXACT round-11 configuration (measured 497.5us, canary-exact): inline hi/lo
// split of both tiles, SA=36, BM=64, 2 CTAs/SM, feat aliases tile smem.
__global__ __launch_bounds__(TH1, 2)
void k_main_kernel(const float* __restrict__ x,
                   const float* __restrict__ lnw,
                   const float* __restrict__ lnb,
                   const int*   __restrict__ dfi) {
    extern __shared__ float dyn[];
    float2* sxA  = (float2*)dyn;                 // [64][SA] (hi,lo)
    float2* spB  = sxA + BM1 * SA;               // [224][SA] (hi,lo)
    float*  feat = dyn;                          // [64][200] — aliases tiles (post-mainloop only)

    const int tid  = threadIdx.x;
    const int lane = tid & 31;
    const int wid  = tid >> 5;                   // 0..7
    const int wm   = wid & 1;                    // m block (32 rows)
    const int wn   = wid >> 1;                   // n block (56 cols)
    const int bm0  = blockIdx.x * BM1;

    for (int q = tid; q < 24 * SA; q += TH1)
        spB[200 * SA + q] = make_float2(0.f, 0.f);

    float acc[2][7][4];
    #pragma unroll
    for (int f = 0; f < 2; f++)
        #pragma unroll
        for (int nf = 0; nf < 7; nf++)
            #pragma unroll
            for (int q = 0; q < 4; q++) acc[f][nf][q] = 0.f;

    const int xr = tid >> 2;                     // x-loader row 0..63
    const int xk = (tid & 3) * 8;                // x-loader k offset

    for (int k0 = 0; k0 < Csz; k0 += 32) {
        __syncthreads();
        // x tile: 64x32, split hi/lo
        {
            const float4* p = reinterpret_cast<const float4*>(
                x + (size_t)(bm0 + xr) * Csz + k0 + xk);
            float4 v0 = p[0], v1 = p[1];
            float vv[8] = {v0.x, v0.y, v0.z, v0.w, v1.x, v1.y, v1.z, v1.w};
            #pragma unroll
            for (int i = 0; i < 8; i++) {
                float h = to_tf32(vv[i]);
                float l = to_tf32(vv[i] - h);
                sxA[xr * SA + xk + i] = make_float2(h, l);
            }
        }
        // proto tile: 200x32, split hi/lo (R11 version — measured faster than
        // the precomputed-HL copy, which doubled L2->SMEM traffic)
        for (int q = tid; q < 200 * 8; q += TH1) {
            int n = q >> 3, kq = (q & 7) * 4;
            float4 v = *reinterpret_cast<const float4*>(
                g_proto + (size_t)n * Csz + k0 + kq);
            float vv[4] = {v.x, v.y, v.z, v.w};
            #pragma unroll
            for (int i = 0; i < 4; i++) {
                float h = to_tf32(vv[i]);
                float l = to_tf32(vv[i] - h);
                spB[n * SA + kq + i] = make_float2(h, l);
            }
        }
        __syncthreads();

        #pragma unroll
        for (int ks = 0; ks < 4; ks++) {
            const int kc = ks * 8 + (lane & 3);
            const int ra = wm * 32 + (lane >> 2);
            float2 Af[2][4];
            #pragma unroll
            for (int f = 0; f < 2; f++) {
                int rb = ra + f * 16;
                Af[f][0] = sxA[rb * SA + kc];
                Af[f][1] = sxA[(rb + 8) * SA + kc];
                Af[f][2] = sxA[rb * SA + kc + 4];
                Af[f][3] = sxA[(rb + 8) * SA + kc + 4];
            }
            #pragma unroll
            for (int nf = 0; nf < 7; nf++) {
                int nn = wn * 56 + nf * 8 + (lane >> 2);
                float2 B0 = spB[nn * SA + kc];
                float2 B1 = spB[nn * SA + kc + 4];
                uint32_t b0h = __float_as_uint(B0.x), b1h = __float_as_uint(B1.x);
                uint32_t b0l = __float_as_uint(B0.y), b1l = __float_as_uint(B1.y);
                #pragma unroll
                for (int f = 0; f < 2; f++) {
                    uint32_t a0h = __float_as_uint(Af[f][0].x);
                    uint32_t a1h = __float_as_uint(Af[f][1].x);
                    uint32_t a2h = __float_as_uint(Af[f][2].x);
                    uint32_t a3h = __float_as_uint(Af[f][3].x);
                    uint32_t a0l = __float_as_uint(Af[f][0].y);
                    uint32_t a1l = __float_as_uint(Af[f][1].y);
                    uint32_t a2l = __float_as_uint(Af[f][2].y);
                    uint32_t a3l = __float_as_uint(Af[f][3].y);
                    mma_tf32(acc[f][nf], a0h, a1h, a2h, a3h, b0h, b1h); // Ah*Bh
                    mma_tf32(acc[f][nf], a0h, a1h, a2h, a3h, b0l, b1l); // Ah*Bl
                    mma_tf32(acc[f][nf], a0l, a1l, a2l, a3l, b0h, b1h); // Al*Bh
                }
            }
        }
    }
    __syncthreads();   // all tile reads done; feat may now alias the tile buffers

    #pragma unroll
    for (int f = 0; f < 2; f++)
        #pragma unroll
        for (int nf = 0; nf < 7; nf++) {
            int row = wm * 32 + f * 16 + (lane >> 2);
            int col = wn * 56 + nf * 8 + 2 * (lane & 3);
            if (col < Ksz) {
                feat[row * Ksz + col]           = acc[f][nf][0];
                feat[row * Ksz + col + 1]       = acc[f][nf][1];
                feat[(row + 8) * Ksz + col]     = acc[f][nf][2];
                feat[(row + 8) * Ksz + col + 1] = acc[f][nf][3];
            }
        }
    __syncthreads();

    const int ktop = Ksz - *dfi;
    for (int rr = 0; rr < 8; rr++) {
        int rloc = wid * 8 + rr;
        int row  = bm0 + rloc;
        float gap = row_select_emit(&feat[rloc * Ksz], lnw, lnb, ktop, row, lane);
        if (lane == 0 && gap < GAPEPS) {
            int p = atomicAdd(&g_fix_cnt, 1);
            g_fix_list[p] = row;
        }
    }
}

// ---------------- fixup v3: 4 rows/block, shared proto staging, R3-exact ----------------
// Groups run in parallel across 256 blocks -> wall time ~ one group.
__global__ __launch_bounds__(256, 1)
void k_fix_kernel(const float* __restrict__ x,
                  const float* __restrict__ lnw,
                  const float* __restrict__ lnb,
                  const int*   __restrict__ dfi) {
    extern __shared__ float fsm[];
    float* xr4 = fsm;                        // [4][2048]   32 KB
    float* sp  = fsm + 4 * Csz;              // [200*33]    26.4 KB
    float* sf  = sp + Ksz * 33;              // [4][224]    3.6 KB
    const int tid  = threadIdx.x;
    const int lane = tid & 31;
    const int nfix = g_fix_cnt;
    const int ktop = Ksz - *dfi;

    for (int base = blockIdx.x * 4; base < nfix; base += gridDim.x * 4) {
        const int nr = (nfix - base < 4) ? (nfix - base) : 4;
        __syncthreads();
        for (int r = 0; r < nr; r++) {
            int row = g_fix_list[base + r];
            for (int q = tid; q < Csz / 4; q += 256)
                reinterpret_cast<float4*>(&xr4[r * Csz])[q] =
                    reinterpret_cast<const float4*>(&x[(size_t)row * Csz])[q];
        }

        float a[4] = {0.f, 0.f, 0.f, 0.f};
        for (int c = 0; c < Csz; c += 32) {
            __syncthreads();
            for (int q = tid; q < Ksz * 8; q += 256) {
                int n = q >> 3, f4 = (q & 7) * 4;
                float4 v = *reinterpret_cast<const float4*>(
                    &g_proto[(size_t)n * Csz + c + f4]);
                float* d = &sp[n * 33 + f4];
                d[0] = v.x; d[1] = v.y; d[2] = v.z; d[3] = v.w;
            }
            __syncthreads();
            if (tid < Ksz) {
                float aT[4] = {0.f, 0.f, 0.f, 0.f};
                #pragma unroll
                for (int kk = 0; kk < 32; kk++) {
                    float s = sp[tid * 33 + kk];
                    #pragma unroll
                    for (int r = 0; r < 4; r++)
                        aT[r] = fmaf(xr4[r * Csz + c + kk], s, aT[r]); // R3 chunk chain
                }
                #pragma unroll
                for (int r = 0; r < 4; r++) a[r] += aT[r];             // R3 chunk merge
            }
        }
        if (tid < Ksz) {
            #pragma unroll
            for (int r = 0; r < 4; r++) sf[r * 224 + tid] = a[r];
        }
        __syncthreads();
        if (tid < 32) {
            for (int r = 0; r < nr; r++) {
                int row = g_fix_list[base + r];
                row_select_emit(&sf[r * 224], lnw, lnb, ktop, row, lane);
            }
        }
    }
}

// ---------------- sparse GEMM2 v4 (round-6 winner, unchanged) ----------------
__global__ __launch_bounds__(256, 2)
void k_out_kernel(const float* __restrict__ fcb,
                  const int*   __restrict__ dfi,
                  float* __restrict__ out) {
    extern __shared__ float4 ws4[];                 // [Ksz][32] float4 = 100KB
    float2* pk = (float2*)(ws4 + Ksz * 32);         // [32][SLOTS] packed (val, idx)

    const int tid  = threadIdx.x;
    const int lane = tid & 31;
    const int wid  = tid >> 5;
    const int cb   = blockIdx.y;
    const int col0 = cb * TNO + lane * 4;
    const bool vall = (col0 + 3) < NCsz;

    for (int q = tid; q < Ksz * 32; q += 256) {
        int k = q >> 5, t4 = q & 31;
        int c = cb * TNO + t4 * 4;
        float4 w;
        if (c + 3 < NCsz) {
            w = *reinterpret_cast<const float4*>(&g_fcwT[(size_t)k * NCsz + c]);
        } else {
            w.x = (c + 0 < NCsz) ? g_fcwT[(size_t)k * NCsz + c + 0] : 0.f;
            w.y = (c + 1 < NCsz) ? g_fcwT[(size_t)k * NCsz + c + 1] : 0.f;
            w.z = (c + 2 < NCsz) ? g_fcwT[(size_t)k * NCsz + c + 2] : 0.f;
            w.w = 0.f;
        }
        ws4[q] = w;
    }

    float4 bb;
    bb.x = (col0 + 0 < NCsz) ? fcb[col0 + 0] : 0.f;
    bb.y = (col0 + 1 < NCsz) ? fcb[col0 + 1] : 0.f;
    bb.z = (col0 + 2 < NCsz) ? fcb[col0 + 2] : 0.f;
    bb.w = (col0 + 3 < NCsz) ? fcb[col0 + 3] : 0.f;
    const int ktop = Ksz - *dfi;
    const int r0   = blockIdx.x * RB;

    for (int batch = 0; batch < RB; batch += 32) {
        __syncthreads();
        for (int q = tid; q < 32 * ktop; q += 256) {
            int r = q / ktop, j = q - r * ktop;
            size_t g = (size_t)(r0 + batch + r) * SLOTS + j;
            pk[r * SLOTS + j] = make_float2(g_sval[g], __int_as_float(g_sidx[g]));
        }
        __syncthreads();

        float4 acc[4];
        #pragma unroll
        for (int r = 0; r < 4; r++) acc[r] = make_float4(0.f, 0.f, 0.f, 0.f);
        const float2* pkr = pk + (wid * 4) * SLOTS;
        #pragma unroll 5
        for (int j = 0; j < ktop; j++) {
            #pragma unroll
            for (int r = 0; r < 4; r++) {
                float2 p = pkr[r * SLOTS + j];
                int idx  = __float_as_int(p.y);
                float4 w = ws4[idx * 32 + lane];
                acc[r].x = fmaf(p.x, w.x, acc[r].x);
                acc[r].y = fmaf(p.x, w.y, acc[r].y);
                acc[r].z = fmaf(p.x, w.z, acc[r].z);
                acc[r].w = fmaf(p.x, w.w, acc[r].w);
            }
        }
        #pragma unroll
        for (int r = 0; r < 4; r++) {
            size_t row = (size_t)(r0 + batch + wid * 4 + r);
            if (vall) {
                float4 o = make_float4(acc[r].x + bb.x, acc[r].y + bb.y,
                                       acc[r].z + bb.z, acc[r].w + bb.w);
                *reinterpret_cast<float4*>(&out[row * NCsz + col0]) = o;
            } else {
                if (col0 + 0 < NCsz) out[row * NCsz + col0 + 0] = acc[r].x + bb.x;
                if (col0 + 1 < NCsz) out[row * NCsz + col0 + 1] = acc[r].y + bb.y;
                if (col0 + 2 < NCsz) out[row * NCsz + col0 + 2] = acc[r].z + bb.z;
            }
        }
    }
}

// ---------------- launch ----------------
extern "C" void kernel_launch(void* const* d_in, const int* in_sizes, int n_in,
                              void* d_out, int out_size) {
    const float* x        = (const float*)d_in[0];
    const float* concepts = (const float*)d_in[1];
    const float* lnw      = (const float*)d_in[2];
    const float* lnb      = (const float*)d_in[3];
    const float* fcw      = (const float*)d_in[4];
    const float* fcb      = (const float*)d_in[5];
    const int*   dfi      = (const int*)d_in[6];
    float* out = (float*)d_out;

    const int smem1 = (BM1 + 224) * SA * (int)sizeof(float2);    // 82,944 B
    const int smem2 = Ksz * 32 * (int)sizeof(float4)
                    + 32 * SLOTS * (int)sizeof(float2);          // 108,544 B
    const int smemF = (4 * Csz + Ksz * 33 + 4 * 224) * (int)sizeof(float); // 62,752 B
    cudaFuncSetAttribute(k_main_kernel,
                         cudaFuncAttributeMaxDynamicSharedMemorySize, smem1);
    cudaFuncSetAttribute(k_out_kernel,
                         cudaFuncAttributeMaxDynamicSharedMemorySize, smem2);
    cudaFuncSetAttribute(k_fix_kernel,
                         cudaFuncAttributeMaxDynamicSharedMemorySize, smemF);

    k_rst_kernel<<<1, 32>>>();
    k_norm_kernel<<<Ksz, 256>>>(concepts);
    dim3 trg((NCsz + 31) / 32, (Ksz + 31) / 32);
    k_tr_kernel<<<trg, dim3(32, 8)>>>(fcw);
    k_main_kernel<<<Bsz / BM1, TH1, smem1>>>(x, lnw, lnb, dfi);
    k_fix_kernel<<<256, 256, smemF>>>(x, lnw, lnb, dfi);
    dim3 g2(Bsz / RB, (NCsz + TNO - 1) / TNO);
    k_out_kernel<<<g2, 256, smem2>>>(fcb, dfi, out);
}

// round 14
// speedup vs baseline: 1.7056x; 1.1906x over previous
#include <cuda_runtime.h>
#include <math.h>
#include <stdint.h>

// Problem constants (fixed by the dataset instance)
#define Bsz   16384
#define Csz   2048
#define Ksz   200
#define NCsz  1000
#define SLOTS 32
#define GAPEPS 3e-4f

// GEMM1 (tensor) tiling
#define BM1 64
#define TH1 256
#define SA  36        // float2 row stride: 36 mod 16 = 4 -> max 2-way bank conflicts

// GEMM2 tiling
#define TNO 128
#define RB  128

// Fixup tiling
#define FR  2         // rows per fixup block

// ---------------- device scratch (no allocations allowed) ----------------
__device__ float g_proto[Ksz * Csz];                    // normalized prototypes (fp32)
__device__ __align__(16) float g_fcwT[Ksz * NCsz];      // fc_w transposed: [K][NC]
__device__ int   g_sidx[Bsz * SLOTS];                   // per-row surviving indices
__device__ float g_sval[Bsz * SLOTS];                   // per-row surviving LN'd values
__device__ int   g_fix_cnt;                             // # near-tie rows
__device__ int   g_fix_list[Bsz];                       // their row ids

// ---------------- tf32 helpers ----------------
__device__ __forceinline__ float to_tf32(float a) {
    uint32_t r;
    asm("cvt.rna.tf32.f32 %0, %1;" : "=r"(r) : "f"(a));
    return __uint_as_float(r);
}
__device__ __forceinline__ void mma_tf32(float* c,
        uint32_t a0, uint32_t a1, uint32_t a2, uint32_t a3,
        uint32_t b0, uint32_t b1) {
    asm volatile(
        "mma.sync.aligned.m16n8k8.row.col.f32.tf32.tf32.f32 "
        "{%0,%1,%2,%3}, {%4,%5,%6,%7}, {%8,%9}, {%0,%1,%2,%3};"
        : "+f"(c[0]), "+f"(c[1]), "+f"(c[2]), "+f"(c[3])
        : "r"(a0), "r"(a1), "r"(a2), "r"(a3), "r"(b0), "r"(b1));
}

// ---------------- shared LN + top-k select + sparse emit (R3-exact) ----------------
// Returns gap = (19th largest |v|) - (20th largest |v|).
__device__ __forceinline__ float row_select_emit(const float* frow,
        const float* __restrict__ lnw, const float* __restrict__ lnb,
        int ktop, int row, int lane) {
    float f[7];
    float s1 = 0.f;
    #pragma unroll
    for (int j = 0; j < 7; j++) {
        int n = lane + 32 * j;
        float v = (n < Ksz) ? frow[n] : 0.f;
        f[j] = v;
        s1 += v;
    }
    #pragma unroll
    for (int off = 16; off > 0; off >>= 1)
        s1 += __shfl_xor_sync(0xffffffffu, s1, off);
    float mu = s1 / (float)Ksz;
    float s2 = 0.f;
    #pragma unroll
    for (int j = 0; j < 7; j++) {
        int n = lane + 32 * j;
        if (n < Ksz) {
            float d = f[j] - mu;
            s2 = fmaf(d, d, s2);
        }
    }
    #pragma unroll
    for (int off = 16; off > 0; off >>= 1)
        s2 += __shfl_xor_sync(0xffffffffu, s2, off);
    float var  = s2 / (float)Ksz;
    float rstd = 1.f / sqrtf(var + 1e-5f);

    float v[7], av[7], sel[7];
    #pragma unroll
    for (int j = 0; j < 7; j++) {
        int n = lane + 32 * j;
        if (n < Ksz) {
            float z = (f[j] - mu) * rstd * lnw[n] + lnb[n];
            v[j] = z; av[j] = fabsf(z); sel[j] = av[j];
        } else { v[j] = 0.f; av[j] = -1.f; sel[j] = -1.f; }
    }
    float t = 0.f, t19 = 3.4e38f;
    for (int it = 0; it < ktop; it++) {
        float lm = sel[0]; int lj = 0;
        #pragma unroll
        for (int j = 1; j < 7; j++) if (sel[j] > lm) { lm = sel[j]; lj = j; }
        float m = lm;
        #pragma unroll
        for (int off = 16; off > 0; off >>= 1)
            m = fmaxf(m, __shfl_xor_sync(0xffffffffu, m, off));
        unsigned ball = __ballot_sync(0xffffffffu, lm == m);
        int leader = __ffs((int)ball) - 1;
        if (lane == leader) sel[lj] = -2.f;
        if (it == ktop - 2) t19 = m;
        t = m;
    }
    int cnt = 0;
    #pragma unroll
    for (int j = 0; j < 7; j++) {
        bool pred = (av[j] - t > 0.f);
        unsigned msk = __ballot_sync(0xffffffffu, pred);
        if (pred) {
            int pos = cnt + __popc(msk & ((1u << lane) - 1u));
            g_sidx[(size_t)row * SLOTS + pos] = lane + 32 * j;
            g_sval[(size_t)row * SLOTS + pos] = v[j];
        }
        cnt += __popc(msk);
    }
    if (lane == 0) {
        for (int p = cnt; p < ktop; p++) {
            g_sidx[(size_t)row * SLOTS + p] = 0;
            g_sval[(size_t)row * SLOTS + p] = 0.f;
        }
    }
    return t19 - t;
}

// ---------------- prep: counter reset + proto normalize + fc_w transpose ----------------
// blocks [0,200): normalize (arithmetic identical to old k_norm_kernel)
// blocks [200,424): transpose tiles (identical to old k_tr_kernel)
__global__ void k_prep_kernel(const float* __restrict__ concepts,
                              const float* __restrict__ fc_w) {
    __shared__ float red[256];
    __shared__ float nrm;
    __shared__ float tile[32][33];
    const int tid = threadIdx.x;

    if (blockIdx.x == 0 && tid == 0) g_fix_cnt = 0;

    if (blockIdx.x < Ksz) {
        int k = blockIdx.x;
        const float* row = concepts + (size_t)k * Csz;
        float s = 0.f;
        for (int c = tid; c < Csz; c += 256) {
            float v = row[c];
            s = fmaf(v, v, s);
        }
        red[tid] = s;
        __syncthreads();
        for (int off = 128; off > 0; off >>= 1) {
            if (tid < off) red[tid] += red[tid + off];
            __syncthreads();
        }
        if (tid == 0) nrm = fmaxf(sqrtf(red[0]), 1e-12f);
        __syncthreads();
        float n = nrm;
        for (int c = tid; c < Csz; c += 256)
            g_proto[(size_t)k * Csz + c] = row[c] / n;
    } else {
        int bx = blockIdx.x - Ksz;          // 0..223
        int n0 = (bx & 31) * 32;            // 32 n-tiles
        int k0 = (bx >> 5) * 32;            // 7 k-tiles
        int tx = tid & 31;
        int ty = tid >> 5;
        #pragma unroll
        for (int i = 0; i < 32; i += 8) {
            int n = n0 + ty + i, k = k0 + tx;
            tile[ty + i][tx] = (n < NCsz && k < Ksz) ? fc_w[(size_t)n * Ksz + k] : 0.f;
        }
        __syncthreads();
        #pragma unroll
        for (int i = 0; i < 32; i += 8) {
            int k = k0 + ty + i, n = n0 + tx;
            if (k < Ksz && n < NCsz)
                g_fcwT[(size_t)k * NCsz + n] = tile[tx][ty + i];
        }
    }
}

// ---------------- pad: no-op, shifts launch order so ncu captures k_fix ----------------
__global__ void k_pad_kernel() {}

// ---------------- GEMM1: tf32 3-pass tensor-core + fused LN/top-k ----------------
// Byte-identical math to rounds 11/13 (measured 497-501us, canary-exact).
__global__ __launch_bounds__(TH1, 2)
void k_main_kernel(const float* __restrict__ x,
                   const float* __restrict__ lnw,
                   const float* __restrict__ lnb,
                   const int*   __restrict__ dfi) {
    extern __shared__ float dyn[];
    float2* sxA  = (float2*)dyn;                 // [64][SA] (hi,lo)
    float2* spB  = sxA + BM1 * SA;               // [224][SA] (hi,lo)
    float*  feat = dyn;                          // [64][200] — aliases tiles (post-mainloop only)

    const int tid  = threadIdx.x;
    const int lane = tid & 31;
    const int wid  = tid >> 5;                   // 0..7
    const int wm   = wid & 1;                    // m block (32 rows)
    const int wn   = wid >> 1;                   // n block (56 cols)
    const int bm0  = blockIdx.x * BM1;

    for (int q = tid; q < 24 * SA; q += TH1)
        spB[200 * SA + q] = make_float2(0.f, 0.f);

    float acc[2][7][4];
    #pragma unroll
    for (int f = 0; f < 2; f++)
        #pragma unroll
        for (int nf = 0; nf < 7; nf++)
            #pragma unroll
            for (int q = 0; q < 4; q++) acc[f][nf][q] = 0.f;

    const int xr = tid >> 2;                     // x-loader row 0..63
    const int xk = (tid & 3) * 8;                // x-loader k offset

    for (int k0 = 0; k0 < Csz; k0 += 32) {
        __syncthreads();
        // x tile: 64x32, split hi/lo
        {
            const float4* p = reinterpret_cast<const float4*>(
                x + (size_t)(bm0 + xr) * Csz + k0 + xk);
            float4 v0 = p[0], v1 = p[1];
            float vv[8] = {v0.x, v0.y, v0.z, v0.w, v1.x, v1.y, v1.z, v1.w};
            #pragma unroll
            for (int i = 0; i < 8; i++) {
                float h = to_tf32(vv[i]);
                float l = to_tf32(vv[i] - h);
                sxA[xr * SA + xk + i] = make_float2(h, l);
            }
        }
        // proto tile: 200x32, split hi/lo
        for (int q = tid; q < 200 * 8; q += TH1) {
            int n = q >> 3, kq = (q & 7) * 4;
            float4 v = *reinterpret_cast<const float4*>(
                g_proto + (size_t)n * Csz + k0 + kq);
            float vv[4] = {v.x, v.y, v.z, v.w};
            #pragma unroll
            for (int i = 0; i < 4; i++) {
                float h = to_tf32(vv[i]);
                float l = to_tf32(vv[i] - h);
                spB[n * SA + kq + i] = make_float2(h, l);
            }
        }
        __syncthreads();

        #pragma unroll
        for (int ks = 0; ks < 4; ks++) {
            const int kc = ks * 8 + (lane & 3);
            const int ra = wm * 32 + (lane >> 2);
            float2 Af[2][4];
            #pragma unroll
            for (int f = 0; f < 2; f++) {
                int rb = ra + f * 16;
                Af[f][0] = sxA[rb * SA + kc];
                Af[f][1] = sxA[(rb + 8) * SA + kc];
                Af[f][2] = sxA[rb * SA + kc + 4];
                Af[f][3] = sxA[(rb + 8) * SA + kc + 4];
            }
            #pragma unroll
            for (int nf = 0; nf < 7; nf++) {
                int nn = wn * 56 + nf * 8 + (lane >> 2);
                float2 B0 = spB[nn * SA + kc];
                float2 B1 = spB[nn * SA + kc + 4];
                uint32_t b0h = __float_as_uint(B0.x), b1h = __float_as_uint(B1.x);
                uint32_t b0l = __float_as_uint(B0.y), b1l = __float_as_uint(B1.y);
                #pragma unroll
                for (int f = 0; f < 2; f++) {
                    uint32_t a0h = __float_as_uint(Af[f][0].x);
                    uint32_t a1h = __float_as_uint(Af[f][1].x);
                    uint32_t a2h = __float_as_uint(Af[f][2].x);
                    uint32_t a3h = __float_as_uint(Af[f][3].x);
                    uint32_t a0l = __float_as_uint(Af[f][0].y);
                    uint32_t a1l = __float_as_uint(Af[f][1].y);
                    uint32_t a2l = __float_as_uint(Af[f][2].y);
                    uint32_t a3l = __float_as_uint(Af[f][3].y);
                    mma_tf32(acc[f][nf], a0h, a1h, a2h, a3h, b0h, b1h); // Ah*Bh
                    mma_tf32(acc[f][nf], a0h, a1h, a2h, a3h, b0l, b1l); // Ah*Bl
                    mma_tf32(acc[f][nf], a0l, a1l, a2l, a3l, b0h, b1h); // Al*Bh
                }
            }
        }
    }
    __syncthreads();   // all tile reads done; feat may now alias the tile buffers

    #pragma unroll
    for (int f = 0; f < 2; f++)
        #pragma unroll
        for (int nf = 0; nf < 7; nf++) {
            int row = wm * 32 + f * 16 + (lane >> 2);
            int col = wn * 56 + nf * 8 + 2 * (lane & 3);
            if (col < Ksz) {
                feat[row * Ksz + col]           = acc[f][nf][0];
                feat[row * Ksz + col + 1]       = acc[f][nf][1];
                feat[(row + 8) * Ksz + col]     = acc[f][nf][2];
                feat[(row + 8) * Ksz + col + 1] = acc[f][nf][3];
            }
        }
    __syncthreads();

    const int ktop = Ksz - *dfi;
    for (int rr = 0; rr < 8; rr++) {
        int rloc = wid * 8 + rr;
        int row  = bm0 + rloc;
        float gap = row_select_emit(&feat[rloc * Ksz], lnw, lnb, ktop, row, lane);
        if (lane == 0 && gap < GAPEPS) {
            int p = atomicAdd(&g_fix_cnt, 1);
            g_fix_list[p] = row;
        }
    }
}

// ---------------- fixup v4: 2 rows/block, 64-wide staged chunks, R3-exact ----------------
// grid 256: all flagged groups processed in one fully parallel pass.
// Chain order preserved exactly: two 32-kk sub-chains per staged 64-chunk.
__global__ __launch_bounds__(256, 1)
void k_fix_kernel(const float* __restrict__ x,
                  const float* __restrict__ lnw,
                  const float* __restrict__ lnb,
                  const int*   __restrict__ dfi) {
    extern __shared__ float fsm[];
    float* xr = fsm;                         // [FR][2048]   16 KB
    float* sp = fsm + FR * Csz;              // [200*65]     52 KB
    float* sf = sp + Ksz * 65;               // [FR][224]    1.8 KB
    const int tid  = threadIdx.x;
    const int lane = tid & 31;
    const int nfix = g_fix_cnt;
    const int ktop = Ksz - *dfi;

    for (int base = blockIdx.x * FR; base < nfix; base += gridDim.x * FR) {
        const int nr = (nfix - base < FR) ? (nfix - base) : FR;
        __syncthreads();
        for (int r = 0; r < nr; r++) {
            int row = g_fix_list[base + r];
            for (int q = tid; q < Csz / 4; q += 256)
                reinterpret_cast<float4*>(&xr[r * Csz])[q] =
                    reinterpret_cast<const float4*>(&x[(size_t)row * Csz])[q];
        }

        float a[FR];
        #pragma unroll
        for (int r = 0; r < FR; r++) a[r] = 0.f;

        for (int c = 0; c < Csz; c += 64) {
            __syncthreads();
            // stage proto[:, c:c+64]: coalesced float4 reads, stride-65 smem rows
            for (int q = tid; q < Ksz * 16; q += 256) {
                int n = q >> 4, f4 = (q & 15) * 4;
                float4 v = *reinterpret_cast<const float4*>(
                    &g_proto[(size_t)n * Csz + c + f4]);
                float* d = &sp[n * 65 + f4];
                d[0] = v.x; d[1] = v.y; d[2] = v.z; d[3] = v.w;
            }
            __syncthreads();
            if (tid < Ksz) {
                #pragma unroll
                for (int h = 0; h < 2; h++) {          // sub-chunks c, c+32 in order
                    float aT[FR];
                    #pragma unroll
                    for (int r = 0; r < FR; r++) aT[r] = 0.f;
                    #pragma unroll
                    for (int kk = 0; kk < 32; kk++) {
                        float s = sp[tid * 65 + h * 32 + kk];
                        #pragma unroll
                        for (int r = 0; r < FR; r++)
                            aT[r] = fmaf(xr[r * Csz + c + h * 32 + kk], s, aT[r]); // R3 chain
                    }
                    #pragma unroll
                    for (int r = 0; r < FR; r++) a[r] += aT[r];                    // R3 merge
                }
            }
        }
        if (tid < Ksz) {
            #pragma unroll
            for (int r = 0; r < FR; r++) sf[r * 224 + tid] = a[r];
        }
        __syncthreads();
        if (tid < 32) {
            for (int r = 0; r < nr; r++) {
                int row = g_fix_list[base + r];
                row_select_emit(&sf[r * 224], lnw, lnb, ktop, row, lane);
            }
        }
    }
}

// ---------------- sparse GEMM2 v4 (round-6 winner, unchanged) ----------------
__global__ __launch_bounds__(256, 2)
void k_out_kernel(const float* __restrict__ fcb,
                  const int*   __restrict__ dfi,
                  float* __restrict__ out) {
    extern __shared__ float4 ws4[];                 // [Ksz][32] float4 = 100KB
    float2* pk = (float2*)(ws4 + Ksz * 32);         // [32][SLOTS] packed (val, idx)

    const int tid  = threadIdx.x;
    const int lane = tid & 31;
    const int wid  = tid >> 5;
    const int cb   = blockIdx.y;
    const int col0 = cb * TNO + lane * 4;
    const bool vall = (col0 + 3) < NCsz;

    for (int q = tid; q < Ksz * 32; q += 256) {
        int k = q >> 5, t4 = q & 31;
        int c = cb * TNO + t4 * 4;
        float4 w;
        if (c + 3 < NCsz) {
            w = *reinterpret_cast<const float4*>(&g_fcwT[(size_t)k * NCsz + c]);
        } else {
            w.x = (c + 0 < NCsz) ? g_fcwT[(size_t)k * NCsz + c + 0] : 0.f;
            w.y = (c + 1 < NCsz) ? g_fcwT[(size_t)k * NCsz + c + 1] : 0.f;
            w.z = (c + 2 < NCsz) ? g_fcwT[(size_t)k * NCsz + c + 2] : 0.f;
            w.w = 0.f;
        }
        ws4[q] = w;
    }

    float4 bb;
    bb.x = (col0 + 0 < NCsz) ? fcb[col0 + 0] : 0.f;
    bb.y = (col0 + 1 < NCsz) ? fcb[col0 + 1] : 0.f;
    bb.z = (col0 + 2 < NCsz) ? fcb[col0 + 2] : 0.f;
    bb.w = (col0 + 3 < NCsz) ? fcb[col0 + 3] : 0.f;
    const int ktop = Ksz - *dfi;
    const int r0   = blockIdx.x * RB;

    for (int batch = 0; batch < RB; batch += 32) {
        __syncthreads();
        for (int q = tid; q < 32 * ktop; q += 256) {
            int r = q / ktop, j = q - r * ktop;
            size_t g = (size_t)(r0 + batch + r) * SLOTS + j;
            pk[r * SLOTS + j] = make_float2(g_sval[g], __int_as_float(g_sidx[g]));
        }
        __syncthreads();

        float4 acc[4];
        #pragma unroll
        for (int r = 0; r < 4; r++) acc[r] = make_float4(0.f, 0.f, 0.f, 0.f);
        const float2* pkr = pk + (wid * 4) * SLOTS;
        #pragma unroll 5
        for (int j = 0; j < ktop; j++) {
            #pragma unroll
            for (int r = 0; r < 4; r++) {
                float2 p = pkr[r * SLOTS + j];
                int idx  = __float_as_int(p.y);
                float4 w = ws4[idx * 32 + lane];
                acc[r].x = fmaf(p.x, w.x, acc[r].x);
                acc[r].y = fmaf(p.x, w.y, acc[r].y);
                acc[r].z = fmaf(p.x, w.z, acc[r].z);
                acc[r].w = fmaf(p.x, w.w, acc[r].w);
            }
        }
        #pragma unroll
        for (int r = 0; r < 4; r++) {
            size_t row = (size_t)(r0 + batch + wid * 4 + r);
            if (vall) {
                float4 o = make_float4(acc[r].x + bb.x, acc[r].y + bb.y,
                                       acc[r].z + bb.z, acc[r].w + bb.w);
                *reinterpret_cast<float4*>(&out[row * NCsz + col0]) = o;
            } else {
                if (col0 + 0 < NCsz) out[row * NCsz + col0 + 0] = acc[r].x + bb.x;
                if (col0 + 1 < NCsz) out[row * NCsz + col0 + 1] = acc[r].y + bb.y;
                if (col0 + 2 < NCsz) out[row * NCsz + col0 + 2] = acc[r].z + bb.z;
            }
        }
    }
}

// ---------------- launch ----------------
extern "C" void kernel_launch(void* const* d_in, const int* in_sizes, int n_in,
                              void* d_out, int out_size) {
    const float* x        = (const float*)d_in[0];
    const float* concepts = (const float*)d_in[1];
    const float* lnw      = (const float*)d_in[2];
    const float* lnb      = (const float*)d_in[3];
    const float* fcw      = (const float*)d_in[4];
    const float* fcb      = (const float*)d_in[5];
    const int*   dfi      = (const int*)d_in[6];
    float* out = (float*)d_out;

    const int smem1 = (BM1 + 224) * SA * (int)sizeof(float2);    // 82,944 B
    const int smem2 = Ksz * 32 * (int)sizeof(float4)
                    + 32 * SLOTS * (int)sizeof(float2);          // 108,544 B
    const int smemF = (FR * Csz + Ksz * 65 + FR * 224) * (int)sizeof(float); // 70,176 B
    cudaFuncSetAttribute(k_main_kernel,
                         cudaFuncAttributeMaxDynamicSharedMemorySize, smem1);
    cudaFuncSetAttribute(k_out_kernel,
                         cudaFuncAttributeMaxDynamicSharedMemorySize, smem2);
    cudaFuncSetAttribute(k_fix_kernel,
                         cudaFuncAttributeMaxDynamicSharedMemorySize, smemF);

    // Launch order chosen so the ncu capture (4th launch) lands on k_fix.
    k_prep_kernel<<<Ksz + 224, 256>>>(concepts, fcw);   // 1: norm + transpose + rst
    k_pad_kernel<<<1, 32>>>();                          // 2: no-op spacer
    k_main_kernel<<<Bsz / BM1, TH1, smem1>>>(x, lnw, lnb, dfi);   // 3
    k_fix_kernel<<<256, 256, smemF>>>(x, lnw, lnb, dfi);          // 4 (profiled)
    dim3 g2(Bsz / RB, (NCsz + TNO - 1) / TNO);
    k_out_kernel<<<g2, 256, smem2>>>(fcb, dfi, out);              // 5
}